// round 12
// baseline (speedup 1.0000x reference)
#include <cuda_runtime.h>
#include <cstdint>

// ---------------- problem constants (fixed shapes) ----------------
#define N_IMG   8
#define K_ANC   9
#define HH      120
#define WW      120
#define M_GT    64
#define A_ANCH  (HH*WW*K_ANC)      /* 129600 */
#define HWSZ    (HH*WW)            /* 14400  */
#define IMG_SZ  1920.0f
#define KPOS    128
#define KNEG    60
#define CAP     4096                /* survivor capacity in shared */
#define TIE_CAP 128

// static pre-filter thresholds (float bit patterns; u >= T -> high tier)
#define TP_HI   0x3F400000u         /* 0.75      : keep ~1/4  of positives */
#define TN_HI   0x3F7C0000u         /* 0.984375  : keep ~1/64 of negatives */

// ---------------- static device scratch (no allocations) ----------------
__device__ uint2  g_pos[N_IMG * A_ANCH];   // low tier grows up, high tier grows down
__device__ uint2  g_neg[N_IMG * A_ANCH];
__device__ int    g_cnt[N_IMG * 4];        // [n][0]=pos_lo 1=pos_hi 2=neg_lo 3=neg_hi
__device__ float4 g_part[N_IMG][2];        // (bce, pred, l1, count)
__device__ int    g_ticket;                // zero-init; reset by last finalizer

struct Keys { unsigned kp0[N_IMG], kp1[N_IMG], kn0[N_IMG], kn1[N_IMG]; };

// ---------------- threefry2x32 (JAX-exact) ----------------
__host__ __device__ __forceinline__ unsigned rotl32(unsigned x, int d) {
    return (x << d) | (x >> (32 - d));
}
__host__ __device__ __forceinline__ void tf2x32(unsigned k0, unsigned k1,
                                                unsigned x0, unsigned x1,
                                                unsigned& o0, unsigned& o1) {
    unsigned ks2 = k0 ^ k1 ^ 0x1BD11BDAu;
    x0 += k0; x1 += k1;
#define TFR(r) { x0 += x1; x1 = rotl32(x1, r); x1 ^= x0; }
    TFR(13) TFR(15) TFR(26) TFR(6)   x0 += k1;  x1 += ks2 + 1u;
    TFR(17) TFR(29) TFR(16) TFR(24)  x0 += ks2; x1 += k0  + 2u;
    TFR(13) TFR(15) TFR(26) TFR(6)   x0 += k0;  x1 += k1  + 3u;
    TFR(17) TFR(29) TFR(16) TFR(24)  x0 += k1;  x1 += ks2 + 4u;
    TFR(13) TFR(15) TFR(26) TFR(6)   x0 += ks2; x1 += k0  + 5u;
#undef TFR
    o0 = x0; o1 = x1;
}

__device__ __forceinline__ unsigned ubits(unsigned k0, unsigned k1, int i) {
    unsigned o0, o1;
    tf2x32(k0, k1, 0u, (unsigned)i, o0, o1);
    unsigned b = o0 ^ o1;
    float u = __uint_as_float((b >> 9) | 0x3f800000u) - 1.0f;   // [0,1)
    return __float_as_uint(u);
}

// ---------------- geometry helpers ----------------
__device__ __forceinline__ void anchor_box(int k, int h, int w,
                                           float& ax1, float& ay1, float& ax2, float& ay2) {
    int r = k / 3, s = k % 3;
    float scale = (s == 0) ? 8.0f : ((s == 1) ? 16.0f : 32.0f);
    float sq2 = sqrtf(2.0f), sqh = sqrtf(0.5f);
    float srw = (r == 0) ? sq2 : ((r == 1) ? 1.0f : sqh);
    float srh = (r == 0) ? sqh : ((r == 1) ? 1.0f : sq2);
    float wsz = __fmul_rn(16.0f * scale, srw);
    float hsz = __fmul_rn(16.0f * scale, srh);
    float cx = __fmul_rn((float)w + 0.5f, 16.0f);
    float cy = __fmul_rn((float)h + 0.5f, 16.0f);
    float hw2 = __fmul_rn(wsz, 0.5f), hh2 = __fmul_rn(hsz, 0.5f);
    ax1 = __fsub_rn(cx, hw2); ay1 = __fsub_rn(cy, hh2);
    ax2 = __fadd_rn(cx, hw2); ay2 = __fadd_rn(cy, hh2);
}

__device__ __forceinline__ void region_box(const float* __restrict__ deltas,
                                           int n, int k, int h, int w,
                                           float ax1, float ay1, float ax2, float ay2,
                                           float& rx1, float& ry1, float& rx2, float& ry2) {
    int db = ((n * 4 * K_ANC + k * 4) * HH + h) * WW + w;
    rx1 = fminf(fmaxf(__fadd_rn(ax1, deltas[db          ]), 0.0f), IMG_SZ);
    ry1 = fminf(fmaxf(__fadd_rn(ay1, deltas[db +   HWSZ ]), 0.0f), IMG_SZ);
    rx2 = fminf(fmaxf(__fadd_rn(ax2, deltas[db + 2*HWSZ ]), 0.0f), IMG_SZ);
    ry2 = fminf(fmaxf(__fadd_rn(ay2, deltas[db + 3*HWSZ ]), 0.0f), IMG_SZ);
}

__device__ __forceinline__ int cls_index(int n, int a) {
    int k = a % K_ANC; int hw = a / K_ANC; int w = hw % WW; int h = hw / WW;
    return ((n * K_ANC + k) * HH + h) * WW + w;
}

__device__ __forceinline__ float softplusf(float x) {
    return fmaxf(x, 0.0f) + log1pf(expf(-fabsf(x)));
}
__device__ __forceinline__ float sl1(float d) {
    float ad = fabsf(d);
    return (ad < 0.1f) ? (0.5f * d * d / 0.1f) : (ad - 0.05f);
}

__device__ void pos_contrib(const float* __restrict__ cls, const float* __restrict__ deltas,
                            const float* __restrict__ gt, int n, int a, int m,
                            float& bce, float& pred, float& l1) {
    int k = a % K_ANC; int hw = a / K_ANC; int w = hw % WW; int h = hw / WW;
    float ax1, ay1, ax2, ay2;
    anchor_box(k, h, w, ax1, ay1, ax2, ay2);
    float rx1, ry1, rx2, ry2;
    region_box(deltas, n, k, h, w, ax1, ay1, ax2, ay2, rx1, ry1, rx2, ry2);
    float aw = __fsub_rn(ax2, ax1), ah = __fsub_rn(ay2, ay1);
    float acx = ax1 + 0.5f * aw, acy = ay1 + 0.5f * ah;
    float bw = fmaxf(__fsub_rn(rx2, rx1), 1e-6f), bh = fmaxf(__fsub_rn(ry2, ry1), 1e-6f);
    float bcx = rx1 + 0.5f * bw, bcy = ry1 + 0.5f * bh;
    float tp0 = (bcx - acx) / aw, tp1 = (bcy - acy) / ah;
    float tp2 = logf(bw / aw),    tp3 = logf(bh / ah);
    const float* g = gt + (n * M_GT + m) * 4;
    float gw = fmaxf(__fsub_rn(g[2], g[0]), 1e-6f), gh = fmaxf(__fsub_rn(g[3], g[1]), 1e-6f);
    float gcx = g[0] + 0.5f * gw, gcy = g[1] + 0.5f * gh;
    float tg0 = (gcx - acx) / aw, tg1 = (gcy - acy) / ah;
    float tg2 = logf(gw / aw),    tg3 = logf(gh / ah);
    l1 += sl1(tp0 - tg0) + sl1(tp1 - tg1) + sl1(tp2 - tg2) + sl1(tp3 - tg3);
    float x = cls[((n * K_ANC + k) * HH + h) * WW + w];
    bce += softplusf(-x); pred += x;
}

// ---------------- kernel 1: region + IoU match + tiered compaction ----------------
#define K1_THREADS 320
__global__ __launch_bounds__(K1_THREADS, 6) void k_match(
        const float* __restrict__ deltas, const float* __restrict__ gt, Keys keys) {
    int n = blockIdx.y;
    __shared__ float4 sg[M_GT];
    __shared__ float  sag[M_GT];
    __shared__ int    scnt[4];
    __shared__ int    sbase[4];
    __shared__ int    wboff[K1_THREADS / 32][4];
    int tid = threadIdx.x;
    if (tid < M_GT) {
        float4 b = reinterpret_cast<const float4*>(gt)[n * M_GT + tid];
        sg[tid] = b;
        sag[tid] = __fmul_rn(fmaxf(__fsub_rn(b.z, b.x), 0.0f),
                             fmaxf(__fsub_rn(b.w, b.y), 0.0f));
    }
    if (tid < 4) scnt[tid] = 0;
    __syncthreads();

    int t = blockIdx.x * K1_THREADS + tid;
    int k = t / HWSZ; int hw = t % HWSZ; int h = hw / WW; int w = hw % WW;
    int a = hw * K_ANC + k;

    float ax1, ay1, ax2, ay2;
    anchor_box(k, h, w, ax1, ay1, ax2, ay2);
    float rx1, ry1, rx2, ry2;
    region_box(deltas, n, k, h, w, ax1, ay1, ax2, ay2, rx1, ry1, rx2, ry2);
    float ab = __fmul_rn(fmaxf(__fsub_rn(rx2, rx1), 0.0f),
                         fmaxf(__fsub_rn(ry2, ry1), 0.0f));

    // warp-union bbox (skipped GTs provably have inter == 0 for every lane)
    float wx1 = rx1, wy1 = ry1, wx2 = rx2, wy2 = ry2;
#pragma unroll
    for (int o = 16; o > 0; o >>= 1) {
        wx1 = fminf(wx1, __shfl_xor_sync(0xffffffffu, wx1, o));
        wy1 = fminf(wy1, __shfl_xor_sync(0xffffffffu, wy1, o));
        wx2 = fmaxf(wx2, __shfl_xor_sync(0xffffffffu, wx2, o));
        wy2 = fmaxf(wy2, __shfl_xor_sync(0xffffffffu, wy2, o));
    }

    // ballot-compacted survivor masks: lane tests GT[lane] and GT[lane+32]
    int lane = tid & 31;
    float4 gA = sg[lane];
    float4 gB = sg[lane + 32];
    bool oA = (wx2 > gA.x) && (gA.z > wx1) && (wy2 > gA.y) && (gA.w > wy1);
    bool oB = (wx2 > gB.x) && (gB.z > wx1) && (wy2 > gB.y) && (gB.w > wy1);
    unsigned mA = __ballot_sync(0xffffffffu, oA);
    unsigned mB = __ballot_sync(0xffffffffu, oB);

    // 2-way ILP survivor loop over combined 64-bit mask (increasing m order)
    float best = 0.0f; int arg = 0;
    unsigned long long M = (unsigned long long)mA | ((unsigned long long)mB << 32);
    while (M) {
        int m1 = __ffsll((long long)M) - 1; M &= M - 1;
        int m2 = -1;
        if (M) { m2 = __ffsll((long long)M) - 1; M &= M - 1; }
        float4 g1 = sg[m1]; float a1 = sag[m1];
        float ix1 = fmaxf(rx1, g1.x), iy1 = fmaxf(ry1, g1.y);
        float ix2 = fminf(rx2, g1.z), iy2 = fminf(ry2, g1.w);
        float inter1 = __fmul_rn(fmaxf(__fsub_rn(ix2, ix1), 0.0f),
                                 fmaxf(__fsub_rn(iy2, iy1), 0.0f));
        float den1 = __fadd_rn(__fsub_rn(__fadd_rn(ab, a1), inter1), 1e-6f);
        float inter2 = 0.0f, den2 = 1.0f;
        if (m2 >= 0) {
            float4 g2 = sg[m2]; float a2 = sag[m2];
            float jx1 = fmaxf(rx1, g2.x), jy1 = fmaxf(ry1, g2.y);
            float jx2 = fminf(rx2, g2.z), jy2 = fminf(ry2, g2.w);
            inter2 = __fmul_rn(fmaxf(__fsub_rn(jx2, jx1), 0.0f),
                               fmaxf(__fsub_rn(jy2, jy1), 0.0f));
            den2 = __fadd_rn(__fsub_rn(__fadd_rn(ab, a2), inter2), 1e-6f);
        }
        // in-order best updates (exact first-tie argmax semantics)
        if (inter1 > __fmul_rn(__fmul_rn(best, den1), 0.9999995f) && inter1 > 0.0f) {
            float iou = __fdiv_rn(inter1, den1);
            if (iou > best) { best = iou; arg = m1; }
        }
        if (m2 >= 0 &&
            inter2 > __fmul_rn(__fmul_rn(best, den2), 0.9999995f) && inter2 > 0.0f) {
            float iou = __fdiv_rn(inter2, den2);
            if (iou > best) { best = iou; arg = m2; }
        }
    }

    int match = (best >= 0.4f) ? arg : ((best < 0.1f) ? -1 : -2);
    unsigned ub = 0u;
    if (match >= 0)       ub = ubits(keys.kp0[n], keys.kp1[n], a);
    else if (match == -1) ub = ubits(keys.kn0[n], keys.kn1[n], a);
    bool isp = (match >= 0) && (ub != 0u);
    bool isn = (match == -1) && (ub != 0u);
    bool hip = isp && (ub >= TP_HI);
    bool hin = isn && (ub >= TN_HI);

    int wid = tid >> 5;
    unsigned m0 = __ballot_sync(0xffffffffu, isp && !hip);
    unsigned m1b = __ballot_sync(0xffffffffu, hip);
    unsigned m2b = __ballot_sync(0xffffffffu, isn && !hin);
    unsigned m3b = __ballot_sync(0xffffffffu, hin);
    if (lane == 0) {
        wboff[wid][0] = atomicAdd(&scnt[0], __popc(m0));
        wboff[wid][1] = atomicAdd(&scnt[1], __popc(m1b));
        wboff[wid][2] = atomicAdd(&scnt[2], __popc(m2b));
        wboff[wid][3] = atomicAdd(&scnt[3], __popc(m3b));
    }
    __syncthreads();
    if (tid < 4) sbase[tid] = atomicAdd(&g_cnt[n * 4 + tid], scnt[tid]);
    __syncthreads();
    unsigned lm = (1u << lane) - 1u;
    if (isp) {
        uint2 e = make_uint2(ub, (unsigned)a | ((unsigned)arg << 17));
        if (hip) {
            int p = sbase[1] + wboff[wid][1] + __popc(m1b & lm);
            g_pos[n * A_ANCH + (A_ANCH - 1 - p)] = e;
        } else {
            int p = sbase[0] + wboff[wid][0] + __popc(m0 & lm);
            g_pos[n * A_ANCH + p] = e;
        }
    }
    if (isn) {
        uint2 e = make_uint2(ub, (unsigned)a);
        if (hin) {
            int p = sbase[3] + wboff[wid][3] + __popc(m3b & lm);
            g_neg[n * A_ANCH + (A_ANCH - 1 - p)] = e;
        } else {
            int p = sbase[2] + wboff[wid][2] + __popc(m2b & lm);
            g_neg[n * A_ANCH + p] = e;
        }
    }
}

// ---------------- kernel 2: exact top-K via radix select + loss reduce ----------------
#define K2_THREADS 1024
#define K2_WARPS   (K2_THREADS / 32)

__global__ __launch_bounds__(K2_THREADS) void k_select(
        const float* __restrict__ cls, const float* __restrict__ deltas,
        const float* __restrict__ gt, float* out, int out_size) {
    int bx = blockIdx.x;
    int n = bx >> 1, cat = bx & 1;                 // 0 = pos, 1 = neg
    int tid = threadIdx.x;
    int wid = tid >> 5, lane = tid & 31;
    const uint2* base = (cat ? g_neg : g_pos) + n * A_ANCH;

    __shared__ int sClo, sChi;
    if (tid == 0) {
        sClo = g_cnt[n * 4 + cat * 2 + 0];
        sChi = g_cnt[n * 4 + cat * 2 + 1];
        g_cnt[n * 4 + cat * 2 + 0] = 0;            // single-owner read+reset
        g_cnt[n * 4 + cat * 2 + 1] = 0;
    }
    __syncthreads();
    int Clo = sClo, Chi = sChi;
    int Ctot = Clo + Chi;
    int K = cat ? KNEG : KPOS;
    int need = min(K, Ctot);

    // segment view: high tier always; low tier only when high can't cover top-K
    const uint2* segA = base + (A_ANCH - Chi);
    int LA = Chi;
    int LB = (Chi >= need) ? 0 : Clo;
    int L = LA + LB;
    auto LD = [&](int i) -> uint2 { return (i < LA) ? segA[i] : base[i - LA]; };

    __shared__ uint2    ss[CAP];
    __shared__ unsigned stie[TIE_CAP];
    __shared__ int      swarp[K2_WARPS][3];
    __shared__ float    fwarp[K2_WARPS][3];
    __shared__ int      stot[3];
    __shared__ unsigned sT;
    __shared__ int      sS, sLo, sHi, sFlag;
    __shared__ int      hist[256];
    __shared__ unsigned s_sel;
    __shared__ int      s_needr, s_tiecnt, scap;

    unsigned T0 = 1u, T1 = 1u;
    {
        float invC = 1.0f / (float)max(Ctot, 1);
        float u0 = 1.0f - (float)(2 * K) * invC;
        float u1 = 1.0f - (float)(8 * K) * invC;
        T0 = (u0 <= 0.0f) ? 1u : __float_as_uint(u0);
        T1 = (u1 <= 0.0f) ? 1u : __float_as_uint(u1);
    }
    if (tid == 0) scap = 0;
    __syncthreads();

    // ---- single scan: 3 counts + opportunistic atomic capture at T0 ----
    int c0 = 0, c1 = 0, c2 = 0;
    for (int i = tid; i < L; i += K2_THREADS) {
        uint2 e = LD(i);
        unsigned v = e.x;
        c0 += (v >= T0); c1 += (v >= T1); c2++;
        if (v >= T0) {
            int p = atomicAdd(&scap, 1);
            if (p < CAP) ss[p] = e;                // order-free: radix hist + tie sort
        }
    }
#pragma unroll
    for (int o = 16; o > 0; o >>= 1) {
        c0 += __shfl_down_sync(0xffffffffu, c0, o);
        c1 += __shfl_down_sync(0xffffffffu, c1, o);
        c2 += __shfl_down_sync(0xffffffffu, c2, o);
    }
    if (lane == 0) { swarp[wid][0] = c0; swarp[wid][1] = c1; swarp[wid][2] = c2; }
    __syncthreads();
    if (tid < 3) {
        int s = 0;
        for (int q = 0; q < K2_WARPS; q++) s += swarp[q][tid];
        stot[tid] = s;
    }
    __syncthreads();

    int S;
    if (stot[0] >= need && stot[0] <= CAP) {
        S = stot[0];                               // common path: capture already done
    } else {
        unsigned T;
        if (stot[1] >= need && stot[1] <= CAP)      { T = T1; S = stot[1]; }
        else if (stot[2] <= CAP)                    { T = 1u; S = stot[2]; }
        else {
            // exactness backstop: binary-search tightest threshold in [need, CAP]
            if (tid == 0) {
                if (stot[1] >= need) { sLo = (int)T1; sHi = (int)T0; sT = T1; sS = stot[1]; }
                else                 { sLo = (int)1u; sHi = (int)T1; sT = 1u; sS = stot[2]; }
                sFlag = 1;
            }
            __syncthreads();
            for (int iter = 0; iter < 34 && sFlag; iter++) {
                unsigned lo = (unsigned)sLo, hi = (unsigned)sHi;
                if (hi - lo <= 1u) break;
                unsigned mid = lo + ((hi - lo) >> 1);
                int c = 0;
                for (int i = tid; i < L; i += K2_THREADS) c += (LD(i).x >= mid);
#pragma unroll
                for (int o = 16; o > 0; o >>= 1) c += __shfl_down_sync(0xffffffffu, c, o);
                if (lane == 0) swarp[wid][0] = c;
                __syncthreads();
                if (tid == 0) {
                    int s = 0;
                    for (int q = 0; q < K2_WARPS; q++) s += swarp[q][0];
                    if (s >= need) { sLo = (int)mid; sT = mid; sS = s; }
                    else           { sHi = (int)mid; }
                    if (sS <= CAP) sFlag = 0;
                }
                __syncthreads();
            }
            __syncthreads();
            T = sT; S = min(sS, CAP);
        }
        // recapture at T (rare path)
        if (tid == 0) scap = 0;
        __syncthreads();
        for (int i = tid; i < L; i += K2_THREADS) {
            uint2 e = LD(i);
            if (e.x >= T) { int p = atomicAdd(&scap, 1); if (p < CAP) ss[p] = e; }
        }
        __syncthreads();
    }
    if (tid == 0) { s_sel = 0u; s_needr = need; s_tiecnt = 0; }
    __syncthreads();

    // ---- radix select: exact k-th largest value among S captured ----
#pragma unroll 1
    for (int p = 0; p < 4; p++) {
        int shift = 24 - 8 * p;
        if (tid < 256) hist[tid] = 0;
        __syncthreads();
        unsigned selhi = s_sel;
        int nr = s_needr;
        for (int j = tid; j < S; j += K2_THREADS) {
            unsigned v = ss[j].x;
            if (p == 0 || (v >> (shift + 8)) == (selhi >> (shift + 8)))
                atomicAdd(&hist[(v >> shift) & 0xFFu], 1);
        }
        __syncthreads();
        if (wid == 0 && nr > 0) {
            int bbase = 255 - 8 * lane;            // lane covers 8 bins, descending
            int ch = 0;
#pragma unroll
            for (int q = 0; q < 8; q++) ch += hist[bbase - q];
            int pre = ch;
#pragma unroll
            for (int o = 1; o < 32; o <<= 1) {
                int v = __shfl_up_sync(0xffffffffu, pre, o);
                if (lane >= o) pre += v;
            }
            int excl = pre - ch;
            if (excl < nr && nr <= pre) {
                int tgt = nr - excl, cum = 0;
                for (int q = 0; q < 8; q++) {
                    int c = hist[bbase - q];
                    if (cum + c >= tgt) {
                        s_sel = selhi | ((unsigned)(bbase - q) << shift);
                        s_needr = tgt - cum;
                        break;
                    }
                    cum += c;
                }
            }
        }
        __syncthreads();
    }
    unsigned Tk = s_sel;
    int r = s_needr;                               // ties at boundary to take

    // ---- gather boundary ties, sort by anchor index (lowest first) ----
    for (int j = tid; j < S; j += K2_THREADS) {
        if (ss[j].x == Tk) {
            int p = atomicAdd(&s_tiecnt, 1);
            if (p < TIE_CAP) stie[p] = ss[j].y;
        }
    }
    __syncthreads();
    if (tid == 0 && need > 0) {
        int c = min(s_tiecnt, TIE_CAP);
        for (int i = 1; i < c; i++) {              // insertion sort by a = y & 0x1FFFF
            unsigned key = stie[i]; int j = i - 1;
            while (j >= 0 && (stie[j] & 0x1FFFFu) > (key & 0x1FFFFu)) {
                stie[j + 1] = stie[j]; j--;
            }
            stie[j + 1] = key;
        }
    }
    __syncthreads();

    // ---- order-free accumulation: all v > Tk, plus first r ties ----
    float b = 0.0f, p = 0.0f, l = 0.0f;
    if (need > 0) {
        for (int j = tid; j < S; j += K2_THREADS) {
            uint2 e = ss[j];
            if (e.x > Tk) {
                int a = (int)(e.y & 0x1FFFFu);
                if (cat) {
                    float x = cls[cls_index(n, a)];
                    b += softplusf(x); p += x;
                } else {
                    int m = (int)(e.y >> 17);
                    pos_contrib(cls, deltas, gt, n, a, m, b, p, l);
                }
            }
        }
        if (tid < r) {
            unsigned y = stie[tid];
            int a = (int)(y & 0x1FFFFu);
            if (cat) {
                float x = cls[cls_index(n, a)];
                b += softplusf(x); p += x;
            } else {
                int m = (int)(y >> 17);
                pos_contrib(cls, deltas, gt, n, a, m, b, p, l);
            }
        }
    }
#pragma unroll
    for (int o = 16; o > 0; o >>= 1) {
        b += __shfl_down_sync(0xffffffffu, b, o);
        p += __shfl_down_sync(0xffffffffu, p, o);
        l += __shfl_down_sync(0xffffffffu, l, o);
    }
    if (lane == 0) { fwarp[wid][0] = b; fwarp[wid][1] = p; fwarp[wid][2] = l; }
    __syncthreads();

    if (tid == 0) {
        float sb = 0.f, sp = 0.f, sl_ = 0.f;
        for (int q = 0; q < K2_WARPS; q++) {
            sb += fwarp[q][0]; sp += fwarp[q][1]; sl_ += fwarp[q][2];
        }
        g_part[n][cat] = make_float4(sb, sp, sl_, (float)need);
        __threadfence();
        int ticket = atomicAdd(&g_ticket, 1);
        if (ticket == N_IMG * 2 - 1) {
            __threadfence();
            float cl = 0.f, bl = 0.f, fg = 0.f, bg = 0.f, pm = 0.f;
            for (int q = 0; q < N_IMG; q++) {
                volatile float* Pp = (volatile float*)&g_part[q][0];
                volatile float* Gg = (volatile float*)&g_part[q][1];
                float Pb = Pp[0], Pd = Pp[1], Pl = Pp[2], np = Pp[3];
                float Gb = Gg[0], Gd = Gg[1], nn = Gg[3];
                float denom = fmaxf(np + nn, 1.0f);
                cl += (Pb + Gb) / denom;
                bl += Pl / (fmaxf(np, 1.0f) * (float)N_IMG);
                fg += np; bg += nn;
                if (q == N_IMG - 1) pm = (Pd + Gd) / denom;
            }
            out[0] = cl; out[1] = bl; out[2] = bg; out[3] = fg; out[4] = pm;
            for (int i = 5; i < out_size; i++) out[i] = 0.0f;
            g_ticket = 0;
        }
    }
}

// ---------------- host launcher ----------------
extern "C" void kernel_launch(void* const* d_in, const int* in_sizes, int n_in,
                              void* d_out, int out_size) {
    (void)in_sizes; (void)n_in;
    const float* cls    = (const float*)d_in[0];
    const float* deltas = (const float*)d_in[1];
    const float* gt     = (const float*)d_in[2];
    float* out = (float*)d_out;

    Keys keys;
    for (int n = 0; n < N_IMG; n++) {
        unsigned K0, K1;
        tf2x32(0u, 42u, 0u, (unsigned)n, K0, K1);
        unsigned p0, p1, q0, q1;
        tf2x32(K0, K1, 0u, 0u, p0, p1);
        tf2x32(K0, K1, 0u, 1u, q0, q1);
        keys.kp0[n] = p0; keys.kp1[n] = p1;
        keys.kn0[n] = q0; keys.kn1[n] = q1;
    }

    dim3 g1(A_ANCH / K1_THREADS, N_IMG);                   // 405 x 8
    k_match<<<g1, K1_THREADS>>>(deltas, gt, keys);
    k_select<<<N_IMG * 2, K2_THREADS>>>(cls, deltas, gt, out, out_size);
}

// round 13
// speedup vs baseline: 1.0961x; 1.0961x over previous
#include <cuda_runtime.h>
#include <cstdint>

// ---------------- problem constants (fixed shapes) ----------------
#define N_IMG   8
#define K_ANC   9
#define HH      120
#define WW      120
#define M_GT    64
#define A_ANCH  (HH*WW*K_ANC)      /* 129600 */
#define HWSZ    (HH*WW)            /* 14400  */
#define IMG_SZ  1920.0f
#define KPOS    128
#define KNEG    60
#define CAP     4096                /* survivor capacity in shared */
#define TIE_CAP 128

// static pre-filter thresholds (float bit patterns; u >= T -> high tier)
#define TP_HI   0x3F400000u         /* 0.75       : keep ~1/4   of positives */
#define TN_HI   0x3F7F0000u         /* 0.99609375 : keep ~1/256 of negatives */

// ---------------- static device scratch (no allocations) ----------------
__device__ uint2  g_pos[N_IMG * A_ANCH];   // low tier grows up, high tier grows down
__device__ uint2  g_neg[N_IMG * A_ANCH];
__device__ int    g_cnt[N_IMG * 4];        // [n][0]=pos_lo 1=pos_hi 2=neg_lo 3=neg_hi
__device__ float4 g_part[N_IMG][2];        // (bce, pred, l1, count)
__device__ int    g_ticket;                // zero-init; reset by last finalizer

struct Keys { unsigned kp0[N_IMG], kp1[N_IMG], kn0[N_IMG], kn1[N_IMG]; };

// ---------------- threefry2x32 (JAX-exact) ----------------
__host__ __device__ __forceinline__ unsigned rotl32(unsigned x, int d) {
    return (x << d) | (x >> (32 - d));
}
__host__ __device__ __forceinline__ void tf2x32(unsigned k0, unsigned k1,
                                                unsigned x0, unsigned x1,
                                                unsigned& o0, unsigned& o1) {
    unsigned ks2 = k0 ^ k1 ^ 0x1BD11BDAu;
    x0 += k0; x1 += k1;
#define TFR(r) { x0 += x1; x1 = rotl32(x1, r); x1 ^= x0; }
    TFR(13) TFR(15) TFR(26) TFR(6)   x0 += k1;  x1 += ks2 + 1u;
    TFR(17) TFR(29) TFR(16) TFR(24)  x0 += ks2; x1 += k0  + 2u;
    TFR(13) TFR(15) TFR(26) TFR(6)   x0 += k0;  x1 += k1  + 3u;
    TFR(17) TFR(29) TFR(16) TFR(24)  x0 += k1;  x1 += ks2 + 4u;
    TFR(13) TFR(15) TFR(26) TFR(6)   x0 += ks2; x1 += k0  + 5u;
#undef TFR
    o0 = x0; o1 = x1;
}

__device__ __forceinline__ unsigned ubits(unsigned k0, unsigned k1, int i) {
    unsigned o0, o1;
    tf2x32(k0, k1, 0u, (unsigned)i, o0, o1);
    unsigned b = o0 ^ o1;
    float u = __uint_as_float((b >> 9) | 0x3f800000u) - 1.0f;   // [0,1)
    return __float_as_uint(u);
}

// ---------------- geometry helpers ----------------
__device__ __forceinline__ void anchor_box(int k, int h, int w,
                                           float& ax1, float& ay1, float& ax2, float& ay2) {
    int r = k / 3, s = k % 3;
    float scale = (s == 0) ? 8.0f : ((s == 1) ? 16.0f : 32.0f);
    float sq2 = sqrtf(2.0f), sqh = sqrtf(0.5f);
    float srw = (r == 0) ? sq2 : ((r == 1) ? 1.0f : sqh);
    float srh = (r == 0) ? sqh : ((r == 1) ? 1.0f : sq2);
    float wsz = __fmul_rn(16.0f * scale, srw);
    float hsz = __fmul_rn(16.0f * scale, srh);
    float cx = __fmul_rn((float)w + 0.5f, 16.0f);
    float cy = __fmul_rn((float)h + 0.5f, 16.0f);
    float hw2 = __fmul_rn(wsz, 0.5f), hh2 = __fmul_rn(hsz, 0.5f);
    ax1 = __fsub_rn(cx, hw2); ay1 = __fsub_rn(cy, hh2);
    ax2 = __fadd_rn(cx, hw2); ay2 = __fadd_rn(cy, hh2);
}

__device__ __forceinline__ void region_box(const float* __restrict__ deltas,
                                           int n, int k, int h, int w,
                                           float ax1, float ay1, float ax2, float ay2,
                                           float& rx1, float& ry1, float& rx2, float& ry2) {
    int db = ((n * 4 * K_ANC + k * 4) * HH + h) * WW + w;
    rx1 = fminf(fmaxf(__fadd_rn(ax1, deltas[db          ]), 0.0f), IMG_SZ);
    ry1 = fminf(fmaxf(__fadd_rn(ay1, deltas[db +   HWSZ ]), 0.0f), IMG_SZ);
    rx2 = fminf(fmaxf(__fadd_rn(ax2, deltas[db + 2*HWSZ ]), 0.0f), IMG_SZ);
    ry2 = fminf(fmaxf(__fadd_rn(ay2, deltas[db + 3*HWSZ ]), 0.0f), IMG_SZ);
}

__device__ __forceinline__ int cls_index(int n, int a) {
    int k = a % K_ANC; int hw = a / K_ANC; int w = hw % WW; int h = hw / WW;
    return ((n * K_ANC + k) * HH + h) * WW + w;
}

__device__ __forceinline__ float softplusf(float x) {
    return fmaxf(x, 0.0f) + log1pf(expf(-fabsf(x)));
}
__device__ __forceinline__ float sl1(float d) {
    float ad = fabsf(d);
    return (ad < 0.1f) ? (0.5f * d * d / 0.1f) : (ad - 0.05f);
}

__device__ void pos_contrib(const float* __restrict__ cls, const float* __restrict__ deltas,
                            const float* __restrict__ gt, int n, int a, int m,
                            float& bce, float& pred, float& l1) {
    int k = a % K_ANC; int hw = a / K_ANC; int w = hw % WW; int h = hw / WW;
    float ax1, ay1, ax2, ay2;
    anchor_box(k, h, w, ax1, ay1, ax2, ay2);
    float rx1, ry1, rx2, ry2;
    region_box(deltas, n, k, h, w, ax1, ay1, ax2, ay2, rx1, ry1, rx2, ry2);
    float aw = __fsub_rn(ax2, ax1), ah = __fsub_rn(ay2, ay1);
    float acx = ax1 + 0.5f * aw, acy = ay1 + 0.5f * ah;
    float bw = fmaxf(__fsub_rn(rx2, rx1), 1e-6f), bh = fmaxf(__fsub_rn(ry2, ry1), 1e-6f);
    float bcx = rx1 + 0.5f * bw, bcy = ry1 + 0.5f * bh;
    float tp0 = (bcx - acx) / aw, tp1 = (bcy - acy) / ah;
    float tp2 = logf(bw / aw),    tp3 = logf(bh / ah);
    const float* g = gt + (n * M_GT + m) * 4;
    float gw = fmaxf(__fsub_rn(g[2], g[0]), 1e-6f), gh = fmaxf(__fsub_rn(g[3], g[1]), 1e-6f);
    float gcx = g[0] + 0.5f * gw, gcy = g[1] + 0.5f * gh;
    float tg0 = (gcx - acx) / aw, tg1 = (gcy - acy) / ah;
    float tg2 = logf(gw / aw),    tg3 = logf(gh / ah);
    l1 += sl1(tp0 - tg0) + sl1(tp1 - tg1) + sl1(tp2 - tg2) + sl1(tp3 - tg3);
    float x = cls[((n * K_ANC + k) * HH + h) * WW + w];
    bce += softplusf(-x); pred += x;
}

// ---------------- kernel 1: region + IoU match + tiered compaction ----------------
#define K1_THREADS 320
__global__ __launch_bounds__(K1_THREADS, 6) void k_match(
        const float* __restrict__ deltas, const float* __restrict__ gt, Keys keys) {
    int n = blockIdx.y;
    __shared__ float4 sg[M_GT];
    __shared__ float  sag[M_GT];
    __shared__ int    scnt[4];
    __shared__ int    sbase[4];
    __shared__ int    wboff[K1_THREADS / 32][4];
    int tid = threadIdx.x;
    if (tid < M_GT) {
        float4 b = reinterpret_cast<const float4*>(gt)[n * M_GT + tid];
        sg[tid] = b;
        sag[tid] = __fmul_rn(fmaxf(__fsub_rn(b.z, b.x), 0.0f),
                             fmaxf(__fsub_rn(b.w, b.y), 0.0f));
    }
    if (tid < 4) scnt[tid] = 0;
    __syncthreads();

    int t = blockIdx.x * K1_THREADS + tid;
    int k = t / HWSZ; int hw = t % HWSZ; int h = hw / WW; int w = hw % WW;
    int a = hw * K_ANC + k;

    float ax1, ay1, ax2, ay2;
    anchor_box(k, h, w, ax1, ay1, ax2, ay2);
    float rx1, ry1, rx2, ry2;
    region_box(deltas, n, k, h, w, ax1, ay1, ax2, ay2, rx1, ry1, rx2, ry2);
    float ab = __fmul_rn(fmaxf(__fsub_rn(rx2, rx1), 0.0f),
                         fmaxf(__fsub_rn(ry2, ry1), 0.0f));

    // warp-union bbox (skipped GTs provably have inter == 0 for every lane)
    float wx1 = rx1, wy1 = ry1, wx2 = rx2, wy2 = ry2;
#pragma unroll
    for (int o = 16; o > 0; o >>= 1) {
        wx1 = fminf(wx1, __shfl_xor_sync(0xffffffffu, wx1, o));
        wy1 = fminf(wy1, __shfl_xor_sync(0xffffffffu, wy1, o));
        wx2 = fmaxf(wx2, __shfl_xor_sync(0xffffffffu, wx2, o));
        wy2 = fmaxf(wy2, __shfl_xor_sync(0xffffffffu, wy2, o));
    }

    // ballot-compacted survivor masks: lane tests GT[lane] and GT[lane+32]
    int lane = tid & 31;
    float4 gA = sg[lane];
    float4 gB = sg[lane + 32];
    bool oA = (wx2 > gA.x) && (gA.z > wx1) && (wy2 > gA.y) && (gA.w > wy1);
    bool oB = (wx2 > gB.x) && (gB.z > wx1) && (wy2 > gB.y) && (gB.w > wy1);
    unsigned mA = __ballot_sync(0xffffffffu, oA);
    unsigned mB = __ballot_sync(0xffffffffu, oB);

    float best = 0.0f; int arg = 0;
    unsigned mm = mA; int mofs = 0;
#pragma unroll 1
    for (int half = 0; half < 2; half++) {
        while (mm) {
            int m = (__ffs(mm) - 1) + mofs;        // increasing m: first-tie preserved
            mm &= mm - 1;
            float4 g = sg[m];                      // uniform -> LDS broadcast
            float ix1 = fmaxf(rx1, g.x), iy1 = fmaxf(ry1, g.y);
            float ix2 = fminf(rx2, g.z), iy2 = fminf(ry2, g.w);
            float inter = __fmul_rn(fmaxf(__fsub_rn(ix2, ix1), 0.0f),
                                    fmaxf(__fsub_rn(iy2, iy1), 0.0f));
            float den = __fadd_rn(__fsub_rn(__fadd_rn(ab, sag[m]), inter), 1e-6f);
            if (inter > __fmul_rn(__fmul_rn(best, den), 0.9999995f) && inter > 0.0f) {
                float iou = __fdiv_rn(inter, den);
                if (iou > best) { best = iou; arg = m; }
            }
        }
        mm = mB; mofs = 32;
    }

    int match = (best >= 0.4f) ? arg : ((best < 0.1f) ? -1 : -2);
    unsigned ub = 0u;
    if (match >= 0)       ub = ubits(keys.kp0[n], keys.kp1[n], a);
    else if (match == -1) ub = ubits(keys.kn0[n], keys.kn1[n], a);
    bool isp = (match >= 0) && (ub != 0u);
    bool isn = (match == -1) && (ub != 0u);
    bool hip = isp && (ub >= TP_HI);
    bool hin = isn && (ub >= TN_HI);

    int wid = tid >> 5;
    unsigned m0 = __ballot_sync(0xffffffffu, isp && !hip);
    unsigned m1 = __ballot_sync(0xffffffffu, hip);
    unsigned m2 = __ballot_sync(0xffffffffu, isn && !hin);
    unsigned m3 = __ballot_sync(0xffffffffu, hin);
    if (lane == 0) {
        wboff[wid][0] = atomicAdd(&scnt[0], __popc(m0));
        wboff[wid][1] = atomicAdd(&scnt[1], __popc(m1));
        wboff[wid][2] = atomicAdd(&scnt[2], __popc(m2));
        wboff[wid][3] = atomicAdd(&scnt[3], __popc(m3));
    }
    __syncthreads();
    if (tid < 4) sbase[tid] = atomicAdd(&g_cnt[n * 4 + tid], scnt[tid]);
    __syncthreads();
    unsigned lm = (1u << lane) - 1u;
    if (isp) {
        uint2 e = make_uint2(ub, (unsigned)a | ((unsigned)arg << 17));
        if (hip) {
            int p = sbase[1] + wboff[wid][1] + __popc(m1 & lm);
            g_pos[n * A_ANCH + (A_ANCH - 1 - p)] = e;
        } else {
            int p = sbase[0] + wboff[wid][0] + __popc(m0 & lm);
            g_pos[n * A_ANCH + p] = e;
        }
    }
    if (isn) {
        uint2 e = make_uint2(ub, (unsigned)a);
        if (hin) {
            int p = sbase[3] + wboff[wid][3] + __popc(m3 & lm);
            g_neg[n * A_ANCH + (A_ANCH - 1 - p)] = e;
        } else {
            int p = sbase[2] + wboff[wid][2] + __popc(m2 & lm);
            g_neg[n * A_ANCH + p] = e;
        }
    }
}

// ---------------- kernel 2: exact top-K via radix select + loss reduce ----------------
#define K2_THREADS 512
#define K2_WARPS   (K2_THREADS / 32)

__global__ __launch_bounds__(K2_THREADS) void k_select(
        const float* __restrict__ cls, const float* __restrict__ deltas,
        const float* __restrict__ gt, float* out, int out_size) {
    int bx = blockIdx.x;
    int n = bx >> 1, cat = bx & 1;                 // 0 = pos, 1 = neg
    int tid = threadIdx.x;
    int wid = tid >> 5, lane = tid & 31;
    const uint2* base = (cat ? g_neg : g_pos) + n * A_ANCH;

    __shared__ int sClo, sChi;
    if (tid == 0) {
        sClo = g_cnt[n * 4 + cat * 2 + 0];
        sChi = g_cnt[n * 4 + cat * 2 + 1];
        g_cnt[n * 4 + cat * 2 + 0] = 0;            // single-owner read+reset
        g_cnt[n * 4 + cat * 2 + 1] = 0;
    }
    __syncthreads();
    int Clo = sClo, Chi = sChi;
    int Ctot = Clo + Chi;
    int K = cat ? KNEG : KPOS;
    int need = min(K, Ctot);

    // segment view: high tier always; low tier only when high can't cover top-K
    const uint2* segA = base + (A_ANCH - Chi);
    int LA = Chi;
    int LB = (Chi >= need) ? 0 : Clo;
    int L = LA + LB;
    auto LD = [&](int i) -> uint2 { return (i < LA) ? segA[i] : base[i - LA]; };

    __shared__ uint2    ss[CAP];
    __shared__ unsigned stie[TIE_CAP];
    __shared__ int      swarp[K2_WARPS][3];
    __shared__ float    fwarp[K2_WARPS][3];
    __shared__ int      stot[3];
    __shared__ unsigned sT;
    __shared__ int      sS, sLo, sHi, sFlag;
    __shared__ int      hist[256];
    __shared__ unsigned s_sel;
    __shared__ int      s_needr, s_tiecnt, scap;

    unsigned T0 = 1u, T1 = 1u;
    {
        float invC = 1.0f / (float)max(Ctot, 1);
        float u0 = 1.0f - (float)(2 * K) * invC;
        float u1 = 1.0f - (float)(8 * K) * invC;
        T0 = (u0 <= 0.0f) ? 1u : __float_as_uint(u0);
        T1 = (u1 <= 0.0f) ? 1u : __float_as_uint(u1);
    }
    if (tid == 0) scap = 0;
    __syncthreads();

    // ---- single scan: 3 counts + opportunistic atomic capture at T0 ----
    int c0 = 0, c1 = 0, c2 = 0;
    for (int i = tid; i < L; i += K2_THREADS) {
        uint2 e = LD(i);
        unsigned v = e.x;
        c0 += (v >= T0); c1 += (v >= T1); c2++;
        if (v >= T0) {
            int p = atomicAdd(&scap, 1);
            if (p < CAP) ss[p] = e;                // order-free: radix hist + tie sort
        }
    }
#pragma unroll
    for (int o = 16; o > 0; o >>= 1) {
        c0 += __shfl_down_sync(0xffffffffu, c0, o);
        c1 += __shfl_down_sync(0xffffffffu, c1, o);
        c2 += __shfl_down_sync(0xffffffffu, c2, o);
    }
    if (lane == 0) { swarp[wid][0] = c0; swarp[wid][1] = c1; swarp[wid][2] = c2; }
    __syncthreads();
    if (tid < 3) {
        int s = 0;
        for (int q = 0; q < K2_WARPS; q++) s += swarp[q][tid];
        stot[tid] = s;
    }
    __syncthreads();

    int S;
    if (stot[0] >= need && stot[0] <= CAP) {
        S = stot[0];                               // common path: capture already done
    } else {
        unsigned T;
        if (stot[1] >= need && stot[1] <= CAP)      { T = T1; S = stot[1]; }
        else if (stot[2] <= CAP)                    { T = 1u; S = stot[2]; }
        else {
            // exactness backstop: binary-search tightest threshold in [need, CAP]
            if (tid == 0) {
                if (stot[1] >= need) { sLo = (int)T1; sHi = (int)T0; sT = T1; sS = stot[1]; }
                else                 { sLo = (int)1u; sHi = (int)T1; sT = 1u; sS = stot[2]; }
                sFlag = 1;
            }
            __syncthreads();
            for (int iter = 0; iter < 34 && sFlag; iter++) {
                unsigned lo = (unsigned)sLo, hi = (unsigned)sHi;
                if (hi - lo <= 1u) break;
                unsigned mid = lo + ((hi - lo) >> 1);
                int c = 0;
                for (int i = tid; i < L; i += K2_THREADS) c += (LD(i).x >= mid);
#pragma unroll
                for (int o = 16; o > 0; o >>= 1) c += __shfl_down_sync(0xffffffffu, c, o);
                if (lane == 0) swarp[wid][0] = c;
                __syncthreads();
                if (tid == 0) {
                    int s = 0;
                    for (int q = 0; q < K2_WARPS; q++) s += swarp[q][0];
                    if (s >= need) { sLo = (int)mid; sT = mid; sS = s; }
                    else           { sHi = (int)mid; }
                    if (sS <= CAP) sFlag = 0;
                }
                __syncthreads();
            }
            __syncthreads();
            T = sT; S = min(sS, CAP);
        }
        // recapture at T (rare path)
        if (tid == 0) scap = 0;
        __syncthreads();
        for (int i = tid; i < L; i += K2_THREADS) {
            uint2 e = LD(i);
            if (e.x >= T) { int p = atomicAdd(&scap, 1); if (p < CAP) ss[p] = e; }
        }
        __syncthreads();
    }
    if (tid == 0) { s_sel = 0u; s_needr = need; s_tiecnt = 0; }
    __syncthreads();

    // ---- radix select: exact k-th largest value among S captured ----
#pragma unroll 1
    for (int p = 0; p < 4; p++) {
        int shift = 24 - 8 * p;
        if (tid < 256) hist[tid] = 0;
        __syncthreads();
        unsigned selhi = s_sel;
        int nr = s_needr;
        for (int j = tid; j < S; j += K2_THREADS) {
            unsigned v = ss[j].x;
            if (p == 0 || (v >> (shift + 8)) == (selhi >> (shift + 8)))
                atomicAdd(&hist[(v >> shift) & 0xFFu], 1);
        }
        __syncthreads();
        if (wid == 0 && nr > 0) {
            int bbase = 255 - 8 * lane;            // lane covers 8 bins, descending
            int ch = 0;
#pragma unroll
            for (int q = 0; q < 8; q++) ch += hist[bbase - q];
            int pre = ch;
#pragma unroll
            for (int o = 1; o < 32; o <<= 1) {
                int v = __shfl_up_sync(0xffffffffu, pre, o);
                if (lane >= o) pre += v;
            }
            int excl = pre - ch;
            if (excl < nr && nr <= pre) {
                int tgt = nr - excl, cum = 0;
                for (int q = 0; q < 8; q++) {
                    int c = hist[bbase - q];
                    if (cum + c >= tgt) {
                        s_sel = selhi | ((unsigned)(bbase - q) << shift);
                        s_needr = tgt - cum;
                        break;
                    }
                    cum += c;
                }
            }
        }
        __syncthreads();
    }
    unsigned Tk = s_sel;
    int r = s_needr;                               // ties at boundary to take

    // ---- gather boundary ties, sort by anchor index (lowest first) ----
    for (int j = tid; j < S; j += K2_THREADS) {
        if (ss[j].x == Tk) {
            int p = atomicAdd(&s_tiecnt, 1);
            if (p < TIE_CAP) stie[p] = ss[j].y;
        }
    }
    __syncthreads();
    if (tid == 0 && need > 0) {
        int c = min(s_tiecnt, TIE_CAP);
        for (int i = 1; i < c; i++) {              // insertion sort by a = y & 0x1FFFF
            unsigned key = stie[i]; int j = i - 1;
            while (j >= 0 && (stie[j] & 0x1FFFFu) > (key & 0x1FFFFu)) {
                stie[j + 1] = stie[j]; j--;
            }
            stie[j + 1] = key;
        }
    }
    __syncthreads();

    // ---- order-free accumulation: all v > Tk, plus first r ties ----
    float b = 0.0f, p = 0.0f, l = 0.0f;
    if (need > 0) {
        for (int j = tid; j < S; j += K2_THREADS) {
            uint2 e = ss[j];
            if (e.x > Tk) {
                int a = (int)(e.y & 0x1FFFFu);
                if (cat) {
                    float x = cls[cls_index(n, a)];
                    b += softplusf(x); p += x;
                } else {
                    int m = (int)(e.y >> 17);
                    pos_contrib(cls, deltas, gt, n, a, m, b, p, l);
                }
            }
        }
        if (tid < r) {
            unsigned y = stie[tid];
            int a = (int)(y & 0x1FFFFu);
            if (cat) {
                float x = cls[cls_index(n, a)];
                b += softplusf(x); p += x;
            } else {
                int m = (int)(y >> 17);
                pos_contrib(cls, deltas, gt, n, a, m, b, p, l);
            }
        }
    }
#pragma unroll
    for (int o = 16; o > 0; o >>= 1) {
        b += __shfl_down_sync(0xffffffffu, b, o);
        p += __shfl_down_sync(0xffffffffu, p, o);
        l += __shfl_down_sync(0xffffffffu, l, o);
    }
    if (lane == 0) { fwarp[wid][0] = b; fwarp[wid][1] = p; fwarp[wid][2] = l; }
    __syncthreads();

    if (tid == 0) {
        float sb = 0.f, sp = 0.f, sl_ = 0.f;
        for (int q = 0; q < K2_WARPS; q++) {
            sb += fwarp[q][0]; sp += fwarp[q][1]; sl_ += fwarp[q][2];
        }
        g_part[n][cat] = make_float4(sb, sp, sl_, (float)need);
        __threadfence();
        int ticket = atomicAdd(&g_ticket, 1);
        if (ticket == N_IMG * 2 - 1) {
            __threadfence();
            float cl = 0.f, bl = 0.f, fg = 0.f, bg = 0.f, pm = 0.f;
            for (int q = 0; q < N_IMG; q++) {
                volatile float* Pp = (volatile float*)&g_part[q][0];
                volatile float* Gg = (volatile float*)&g_part[q][1];
                float Pb = Pp[0], Pd = Pp[1], Pl = Pp[2], np = Pp[3];
                float Gb = Gg[0], Gd = Gg[1], nn = Gg[3];
                float denom = fmaxf(np + nn, 1.0f);
                cl += (Pb + Gb) / denom;
                bl += Pl / (fmaxf(np, 1.0f) * (float)N_IMG);
                fg += np; bg += nn;
                if (q == N_IMG - 1) pm = (Pd + Gd) / denom;
            }
            out[0] = cl; out[1] = bl; out[2] = bg; out[3] = fg; out[4] = pm;
            for (int i = 5; i < out_size; i++) out[i] = 0.0f;
            g_ticket = 0;
        }
    }
}

// ---------------- host launcher ----------------
extern "C" void kernel_launch(void* const* d_in, const int* in_sizes, int n_in,
                              void* d_out, int out_size) {
    (void)in_sizes; (void)n_in;
    const float* cls    = (const float*)d_in[0];
    const float* deltas = (const float*)d_in[1];
    const float* gt     = (const float*)d_in[2];
    float* out = (float*)d_out;

    Keys keys;
    for (int n = 0; n < N_IMG; n++) {
        unsigned K0, K1;
        tf2x32(0u, 42u, 0u, (unsigned)n, K0, K1);
        unsigned p0, p1, q0, q1;
        tf2x32(K0, K1, 0u, 0u, p0, p1);
        tf2x32(K0, K1, 0u, 1u, q0, q1);
        keys.kp0[n] = p0; keys.kp1[n] = p1;
        keys.kn0[n] = q0; keys.kn1[n] = q1;
    }

    dim3 g1(A_ANCH / K1_THREADS, N_IMG);                   // 405 x 8
    k_match<<<g1, K1_THREADS>>>(deltas, gt, keys);
    k_select<<<N_IMG * 2, K2_THREADS>>>(cls, deltas, gt, out, out_size);
}

// round 14
// speedup vs baseline: 1.1558x; 1.0545x over previous
#include <cuda_runtime.h>
#include <cstdint>

// ---------------- problem constants (fixed shapes) ----------------
#define N_IMG   8
#define K_ANC   9
#define HH      120
#define WW      120
#define M_GT    64
#define A_ANCH  (HH*WW*K_ANC)      /* 129600 */
#define HWSZ    (HH*WW)            /* 14400  */
#define IMG_SZ  1920.0f
#define KPOS    128
#define KNEG    60
#define CAP     4096                /* survivor capacity in shared */
#define TIE_CAP 128
#define RANK_MAX 1024               /* rank-select path limit */

// static pre-filter thresholds (float bit patterns; u >= T -> high tier)
#define TP_HI   0x3F400000u         /* 0.75       : keep ~1/4   of positives */
#define TN_HI   0x3F7F0000u         /* 0.99609375 : keep ~1/256 of negatives */

// ---------------- static device scratch (no allocations) ----------------
__device__ uint2  g_pos[N_IMG * A_ANCH];   // low tier grows up, high tier grows down
__device__ uint2  g_neg[N_IMG * A_ANCH];
__device__ int    g_cnt[N_IMG * 4];        // [n][0]=pos_lo 1=pos_hi 2=neg_lo 3=neg_hi
__device__ float4 g_part[N_IMG][2];        // (bce, pred, l1, count)
__device__ int    g_ticket;                // zero-init; reset by last finalizer

struct Keys { unsigned kp0[N_IMG], kp1[N_IMG], kn0[N_IMG], kn1[N_IMG]; };

// ---------------- threefry2x32 (JAX-exact) ----------------
__host__ __device__ __forceinline__ unsigned rotl32(unsigned x, int d) {
    return (x << d) | (x >> (32 - d));
}
__host__ __device__ __forceinline__ void tf2x32(unsigned k0, unsigned k1,
                                                unsigned x0, unsigned x1,
                                                unsigned& o0, unsigned& o1) {
    unsigned ks2 = k0 ^ k1 ^ 0x1BD11BDAu;
    x0 += k0; x1 += k1;
#define TFR(r) { x0 += x1; x1 = rotl32(x1, r); x1 ^= x0; }
    TFR(13) TFR(15) TFR(26) TFR(6)   x0 += k1;  x1 += ks2 + 1u;
    TFR(17) TFR(29) TFR(16) TFR(24)  x0 += ks2; x1 += k0  + 2u;
    TFR(13) TFR(15) TFR(26) TFR(6)   x0 += k0;  x1 += k1  + 3u;
    TFR(17) TFR(29) TFR(16) TFR(24)  x0 += k1;  x1 += ks2 + 4u;
    TFR(13) TFR(15) TFR(26) TFR(6)   x0 += ks2; x1 += k0  + 5u;
#undef TFR
    o0 = x0; o1 = x1;
}

__device__ __forceinline__ unsigned ubits(unsigned k0, unsigned k1, int i) {
    unsigned o0, o1;
    tf2x32(k0, k1, 0u, (unsigned)i, o0, o1);
    unsigned b = o0 ^ o1;
    float u = __uint_as_float((b >> 9) | 0x3f800000u) - 1.0f;   // [0,1)
    return __float_as_uint(u);
}

// ---------------- geometry helpers ----------------
__device__ __forceinline__ void anchor_box(int k, int h, int w,
                                           float& ax1, float& ay1, float& ax2, float& ay2) {
    int r = k / 3, s = k % 3;
    float scale = (s == 0) ? 8.0f : ((s == 1) ? 16.0f : 32.0f);
    float sq2 = sqrtf(2.0f), sqh = sqrtf(0.5f);
    float srw = (r == 0) ? sq2 : ((r == 1) ? 1.0f : sqh);
    float srh = (r == 0) ? sqh : ((r == 1) ? 1.0f : sq2);
    float wsz = __fmul_rn(16.0f * scale, srw);
    float hsz = __fmul_rn(16.0f * scale, srh);
    float cx = __fmul_rn((float)w + 0.5f, 16.0f);
    float cy = __fmul_rn((float)h + 0.5f, 16.0f);
    float hw2 = __fmul_rn(wsz, 0.5f), hh2 = __fmul_rn(hsz, 0.5f);
    ax1 = __fsub_rn(cx, hw2); ay1 = __fsub_rn(cy, hh2);
    ax2 = __fadd_rn(cx, hw2); ay2 = __fadd_rn(cy, hh2);
}

__device__ __forceinline__ void region_box(const float* __restrict__ deltas,
                                           int n, int k, int h, int w,
                                           float ax1, float ay1, float ax2, float ay2,
                                           float& rx1, float& ry1, float& rx2, float& ry2) {
    int db = ((n * 4 * K_ANC + k * 4) * HH + h) * WW + w;
    rx1 = fminf(fmaxf(__fadd_rn(ax1, deltas[db          ]), 0.0f), IMG_SZ);
    ry1 = fminf(fmaxf(__fadd_rn(ay1, deltas[db +   HWSZ ]), 0.0f), IMG_SZ);
    rx2 = fminf(fmaxf(__fadd_rn(ax2, deltas[db + 2*HWSZ ]), 0.0f), IMG_SZ);
    ry2 = fminf(fmaxf(__fadd_rn(ay2, deltas[db + 3*HWSZ ]), 0.0f), IMG_SZ);
}

__device__ __forceinline__ int cls_index(int n, int a) {
    int k = a % K_ANC; int hw = a / K_ANC; int w = hw % WW; int h = hw / WW;
    return ((n * K_ANC + k) * HH + h) * WW + w;
}

__device__ __forceinline__ float softplusf(float x) {
    return fmaxf(x, 0.0f) + log1pf(expf(-fabsf(x)));
}
__device__ __forceinline__ float sl1(float d) {
    float ad = fabsf(d);
    return (ad < 0.1f) ? (0.5f * d * d / 0.1f) : (ad - 0.05f);
}

__device__ void pos_contrib(const float* __restrict__ cls, const float* __restrict__ deltas,
                            const float* __restrict__ gt, int n, int a, int m,
                            float& bce, float& pred, float& l1) {
    int k = a % K_ANC; int hw = a / K_ANC; int w = hw % WW; int h = hw / WW;
    float ax1, ay1, ax2, ay2;
    anchor_box(k, h, w, ax1, ay1, ax2, ay2);
    float rx1, ry1, rx2, ry2;
    region_box(deltas, n, k, h, w, ax1, ay1, ax2, ay2, rx1, ry1, rx2, ry2);
    float aw = __fsub_rn(ax2, ax1), ah = __fsub_rn(ay2, ay1);
    float acx = ax1 + 0.5f * aw, acy = ay1 + 0.5f * ah;
    float bw = fmaxf(__fsub_rn(rx2, rx1), 1e-6f), bh = fmaxf(__fsub_rn(ry2, ry1), 1e-6f);
    float bcx = rx1 + 0.5f * bw, bcy = ry1 + 0.5f * bh;
    float tp0 = (bcx - acx) / aw, tp1 = (bcy - acy) / ah;
    float tp2 = logf(bw / aw),    tp3 = logf(bh / ah);
    const float* g = gt + (n * M_GT + m) * 4;
    float gw = fmaxf(__fsub_rn(g[2], g[0]), 1e-6f), gh = fmaxf(__fsub_rn(g[3], g[1]), 1e-6f);
    float gcx = g[0] + 0.5f * gw, gcy = g[1] + 0.5f * gh;
    float tg0 = (gcx - acx) / aw, tg1 = (gcy - acy) / ah;
    float tg2 = logf(gw / aw),    tg3 = logf(gh / ah);
    l1 += sl1(tp0 - tg0) + sl1(tp1 - tg1) + sl1(tp2 - tg2) + sl1(tp3 - tg3);
    float x = cls[((n * K_ANC + k) * HH + h) * WW + w];
    bce += softplusf(-x); pred += x;
}

// ---------------- kernel 1: region + IoU match + tiered compaction ----------------
#define K1_THREADS 320
__global__ __launch_bounds__(K1_THREADS, 6) void k_match(
        const float* __restrict__ deltas, const float* __restrict__ gt, Keys keys) {
    int n = blockIdx.y;
    __shared__ float4 sg[M_GT];
    __shared__ float  sag[M_GT];
    __shared__ int    scnt[4];
    __shared__ int    sbase[4];
    __shared__ int    wboff[K1_THREADS / 32][4];
    int tid = threadIdx.x;
    if (tid < M_GT) {
        float4 b = reinterpret_cast<const float4*>(gt)[n * M_GT + tid];
        sg[tid] = b;
        sag[tid] = __fmul_rn(fmaxf(__fsub_rn(b.z, b.x), 0.0f),
                             fmaxf(__fsub_rn(b.w, b.y), 0.0f));
    }
    if (tid < 4) scnt[tid] = 0;
    __syncthreads();

    int t = blockIdx.x * K1_THREADS + tid;
    int k = t / HWSZ; int hw = t % HWSZ; int h = hw / WW; int w = hw % WW;
    int a = hw * K_ANC + k;

    float ax1, ay1, ax2, ay2;
    anchor_box(k, h, w, ax1, ay1, ax2, ay2);
    float rx1, ry1, rx2, ry2;
    region_box(deltas, n, k, h, w, ax1, ay1, ax2, ay2, rx1, ry1, rx2, ry2);
    float ab = __fmul_rn(fmaxf(__fsub_rn(rx2, rx1), 0.0f),
                         fmaxf(__fsub_rn(ry2, ry1), 0.0f));

    // warp-union bbox (skipped GTs provably have inter == 0 for every lane)
    float wx1 = rx1, wy1 = ry1, wx2 = rx2, wy2 = ry2;
#pragma unroll
    for (int o = 16; o > 0; o >>= 1) {
        wx1 = fminf(wx1, __shfl_xor_sync(0xffffffffu, wx1, o));
        wy1 = fminf(wy1, __shfl_xor_sync(0xffffffffu, wy1, o));
        wx2 = fmaxf(wx2, __shfl_xor_sync(0xffffffffu, wx2, o));
        wy2 = fmaxf(wy2, __shfl_xor_sync(0xffffffffu, wy2, o));
    }

    // ballot-compacted survivor masks: lane tests GT[lane] and GT[lane+32]
    int lane = tid & 31;
    float4 gA = sg[lane];
    float4 gB = sg[lane + 32];
    bool oA = (wx2 > gA.x) && (gA.z > wx1) && (wy2 > gA.y) && (gA.w > wy1);
    bool oB = (wx2 > gB.x) && (gB.z > wx1) && (wy2 > gB.y) && (gB.w > wy1);
    unsigned mA = __ballot_sync(0xffffffffu, oA);
    unsigned mB = __ballot_sync(0xffffffffu, oB);

    float best = 0.0f; int arg = 0;
    unsigned mm = mA; int mofs = 0;
#pragma unroll 1
    for (int half = 0; half < 2; half++) {
        while (mm) {
            int m = (__ffs(mm) - 1) + mofs;        // increasing m: first-tie preserved
            mm &= mm - 1;
            float4 g = sg[m];                      // uniform -> LDS broadcast
            float ix1 = fmaxf(rx1, g.x), iy1 = fmaxf(ry1, g.y);
            float ix2 = fminf(rx2, g.z), iy2 = fminf(ry2, g.w);
            float inter = __fmul_rn(fmaxf(__fsub_rn(ix2, ix1), 0.0f),
                                    fmaxf(__fsub_rn(iy2, iy1), 0.0f));
            float den = __fadd_rn(__fsub_rn(__fadd_rn(ab, sag[m]), inter), 1e-6f);
            if (inter > __fmul_rn(__fmul_rn(best, den), 0.9999995f) && inter > 0.0f) {
                float iou = __fdiv_rn(inter, den);
                if (iou > best) { best = iou; arg = m; }
            }
        }
        mm = mB; mofs = 32;
    }

    int match = (best >= 0.4f) ? arg : ((best < 0.1f) ? -1 : -2);
    unsigned ub = 0u;
    if (match >= 0)       ub = ubits(keys.kp0[n], keys.kp1[n], a);
    else if (match == -1) ub = ubits(keys.kn0[n], keys.kn1[n], a);
    bool isp = (match >= 0) && (ub != 0u);
    bool isn = (match == -1) && (ub != 0u);
    bool hip = isp && (ub >= TP_HI);
    bool hin = isn && (ub >= TN_HI);

    int wid = tid >> 5;
    unsigned m0 = __ballot_sync(0xffffffffu, isp && !hip);
    unsigned m1 = __ballot_sync(0xffffffffu, hip);
    unsigned m2 = __ballot_sync(0xffffffffu, isn && !hin);
    unsigned m3 = __ballot_sync(0xffffffffu, hin);
    if (lane == 0) {
        wboff[wid][0] = atomicAdd(&scnt[0], __popc(m0));
        wboff[wid][1] = atomicAdd(&scnt[1], __popc(m1));
        wboff[wid][2] = atomicAdd(&scnt[2], __popc(m2));
        wboff[wid][3] = atomicAdd(&scnt[3], __popc(m3));
    }
    __syncthreads();
    if (tid < 4) sbase[tid] = atomicAdd(&g_cnt[n * 4 + tid], scnt[tid]);
    __syncthreads();
    unsigned lm = (1u << lane) - 1u;
    if (isp) {
        uint2 e = make_uint2(ub, (unsigned)a | ((unsigned)arg << 17));
        if (hip) {
            int p = sbase[1] + wboff[wid][1] + __popc(m1 & lm);
            g_pos[n * A_ANCH + (A_ANCH - 1 - p)] = e;
        } else {
            int p = sbase[0] + wboff[wid][0] + __popc(m0 & lm);
            g_pos[n * A_ANCH + p] = e;
        }
    }
    if (isn) {
        uint2 e = make_uint2(ub, (unsigned)a);
        if (hin) {
            int p = sbase[3] + wboff[wid][3] + __popc(m3 & lm);
            g_neg[n * A_ANCH + (A_ANCH - 1 - p)] = e;
        } else {
            int p = sbase[2] + wboff[wid][2] + __popc(m2 & lm);
            g_neg[n * A_ANCH + p] = e;
        }
    }
}

// ---------------- kernel 2: exact top-K (rank-select fast path) + loss reduce ----------------
#define K2_THREADS 512
#define K2_WARPS   (K2_THREADS / 32)

__global__ __launch_bounds__(K2_THREADS) void k_select(
        const float* __restrict__ cls, const float* __restrict__ deltas,
        const float* __restrict__ gt, float* out, int out_size) {
    int bx = blockIdx.x;
    int n = bx >> 1, cat = bx & 1;                 // 0 = pos, 1 = neg
    int tid = threadIdx.x;
    int wid = tid >> 5, lane = tid & 31;
    const uint2* base = (cat ? g_neg : g_pos) + n * A_ANCH;

    __shared__ int sClo, sChi;
    if (tid == 0) {
        sClo = g_cnt[n * 4 + cat * 2 + 0];
        sChi = g_cnt[n * 4 + cat * 2 + 1];
        g_cnt[n * 4 + cat * 2 + 0] = 0;            // single-owner read+reset
        g_cnt[n * 4 + cat * 2 + 1] = 0;
    }
    __syncthreads();
    int Clo = sClo, Chi = sChi;
    int Ctot = Clo + Chi;
    int K = cat ? KNEG : KPOS;
    int need = min(K, Ctot);

    // segment view: high tier always; low tier only when high can't cover top-K
    const uint2* segA = base + (A_ANCH - Chi);
    int LA = Chi;
    int LB = (Chi >= need) ? 0 : Clo;
    int L = LA + LB;
    auto LD = [&](int i) -> uint2 { return (i < LA) ? segA[i] : base[i - LA]; };

    __shared__ uint2    ss[CAP];
    __shared__ unsigned stie[TIE_CAP];
    __shared__ int      swarp[K2_WARPS][3];
    __shared__ float    fwarp[K2_WARPS][3];
    __shared__ int      stot[3];
    __shared__ unsigned sT;
    __shared__ int      sS, sLo, sHi, sFlag;
    __shared__ int      hist[256];
    __shared__ unsigned s_sel;
    __shared__ int      s_needr, s_tiecnt, scap;

    unsigned T0 = 1u, T1 = 1u;
    {
        float invC = 1.0f / (float)max(Ctot, 1);
        float u0 = 1.0f - __fmul_rn(1.4f, (float)K) * invC;   // tight: E[S] ~ 1.4K
        float u1 = 1.0f - (float)(8 * K) * invC;
        T0 = (u0 <= 0.0f) ? 1u : __float_as_uint(u0);
        T1 = (u1 <= 0.0f) ? 1u : __float_as_uint(u1);
    }
    if (tid == 0) scap = 0;
    __syncthreads();

    // ---- single scan: 3 counts + opportunistic atomic capture at T0 ----
    int c0 = 0, c1 = 0, c2 = 0;
    for (int i = tid; i < L; i += K2_THREADS) {
        uint2 e = LD(i);
        unsigned v = e.x;
        c0 += (v >= T0); c1 += (v >= T1); c2++;
        if (v >= T0) {
            int p = atomicAdd(&scap, 1);
            if (p < CAP) ss[p] = e;                // order-free: rank/radix later
        }
    }
#pragma unroll
    for (int o = 16; o > 0; o >>= 1) {
        c0 += __shfl_down_sync(0xffffffffu, c0, o);
        c1 += __shfl_down_sync(0xffffffffu, c1, o);
        c2 += __shfl_down_sync(0xffffffffu, c2, o);
    }
    if (lane == 0) { swarp[wid][0] = c0; swarp[wid][1] = c1; swarp[wid][2] = c2; }
    __syncthreads();
    if (tid < 3) {
        int s = 0;
        for (int q = 0; q < K2_WARPS; q++) s += swarp[q][tid];
        stot[tid] = s;
    }
    __syncthreads();

    int S;
    if (stot[0] >= need && stot[0] <= CAP) {
        S = stot[0];                               // common path: capture already done
    } else {
        unsigned T;
        if (stot[1] >= need && stot[1] <= CAP)      { T = T1; S = stot[1]; }
        else if (stot[2] <= CAP)                    { T = 1u; S = stot[2]; }
        else {
            // exactness backstop: binary-search tightest threshold in [need, CAP]
            if (tid == 0) {
                if (stot[1] >= need) { sLo = (int)T1; sHi = (int)T0; sT = T1; sS = stot[1]; }
                else                 { sLo = (int)1u; sHi = (int)T1; sT = 1u; sS = stot[2]; }
                sFlag = 1;
            }
            __syncthreads();
            for (int iter = 0; iter < 34 && sFlag; iter++) {
                unsigned lo = (unsigned)sLo, hi = (unsigned)sHi;
                if (hi - lo <= 1u) break;
                unsigned mid = lo + ((hi - lo) >> 1);
                int c = 0;
                for (int i = tid; i < L; i += K2_THREADS) c += (LD(i).x >= mid);
#pragma unroll
                for (int o = 16; o > 0; o >>= 1) c += __shfl_down_sync(0xffffffffu, c, o);
                if (lane == 0) swarp[wid][0] = c;
                __syncthreads();
                if (tid == 0) {
                    int s = 0;
                    for (int q = 0; q < K2_WARPS; q++) s += swarp[q][0];
                    if (s >= need) { sLo = (int)mid; sT = mid; sS = s; }
                    else           { sHi = (int)mid; }
                    if (sS <= CAP) sFlag = 0;
                }
                __syncthreads();
            }
            __syncthreads();
            T = sT; S = min(sS, CAP);
        }
        // recapture at T (rare path)
        if (tid == 0) scap = 0;
        __syncthreads();
        for (int i = tid; i < L; i += K2_THREADS) {
            uint2 e = LD(i);
            if (e.x >= T) { int p = atomicAdd(&scap, 1); if (p < CAP) ss[p] = e; }
        }
        __syncthreads();
    }
    __syncthreads();                               // ss[] fully visible

    float b = 0.0f, p = 0.0f, l = 0.0f;

    if (S <= RANK_MAX) {
        // ---- exact rank-select (lax.top_k semantics, single phase, no syncs) ----
        // rank(v,a) = #{v_i > v} + #{v_i == v && a_i < a}; select iff rank < need
        for (int j = tid; j < S; j += K2_THREADS) {
            uint2 e = ss[j];
            unsigned v = e.x, aj = e.y & 0x1FFFFu;
            int rank = 0;
            for (int i = 0; i < S; i++) {          // lockstep -> LDS broadcast
                uint2 f = ss[i];
                unsigned ai = f.y & 0x1FFFFu;
                rank += (f.x > v) || (f.x == v && ai < aj);
            }
            if (rank < need) {
                int a = (int)aj;
                if (cat) {
                    float x = cls[cls_index(n, a)];
                    b += softplusf(x); p += x;
                } else {
                    int m = (int)(e.y >> 17);
                    pos_contrib(cls, deltas, gt, n, a, m, b, p, l);
                }
            }
        }
    } else {
        // ---- fallback: radix select + tie handling (rare: S > RANK_MAX) ----
        if (tid == 0) { s_sel = 0u; s_needr = need; s_tiecnt = 0; }
        __syncthreads();
#pragma unroll 1
        for (int ps = 0; ps < 4; ps++) {
            int shift = 24 - 8 * ps;
            if (tid < 256) hist[tid] = 0;
            __syncthreads();
            unsigned selhi = s_sel;
            int nr = s_needr;
            for (int j = tid; j < S; j += K2_THREADS) {
                unsigned v = ss[j].x;
                if (ps == 0 || (v >> (shift + 8)) == (selhi >> (shift + 8)))
                    atomicAdd(&hist[(v >> shift) & 0xFFu], 1);
            }
            __syncthreads();
            if (wid == 0 && nr > 0) {
                int bbase = 255 - 8 * lane;
                int ch = 0;
#pragma unroll
                for (int q = 0; q < 8; q++) ch += hist[bbase - q];
                int pre = ch;
#pragma unroll
                for (int o = 1; o < 32; o <<= 1) {
                    int v = __shfl_up_sync(0xffffffffu, pre, o);
                    if (lane >= o) pre += v;
                }
                int excl = pre - ch;
                if (excl < nr && nr <= pre) {
                    int tgt = nr - excl, cum = 0;
                    for (int q = 0; q < 8; q++) {
                        int c = hist[bbase - q];
                        if (cum + c >= tgt) {
                            s_sel = selhi | ((unsigned)(bbase - q) << shift);
                            s_needr = tgt - cum;
                            break;
                        }
                        cum += c;
                    }
                }
            }
            __syncthreads();
        }
        unsigned Tk = s_sel;
        int r = s_needr;
        for (int j = tid; j < S; j += K2_THREADS) {
            if (ss[j].x == Tk) {
                int q = atomicAdd(&s_tiecnt, 1);
                if (q < TIE_CAP) stie[q] = ss[j].y;
            }
        }
        __syncthreads();
        if (tid == 0 && need > 0) {
            int c = min(s_tiecnt, TIE_CAP);
            for (int i = 1; i < c; i++) {
                unsigned key = stie[i]; int j = i - 1;
                while (j >= 0 && (stie[j] & 0x1FFFFu) > (key & 0x1FFFFu)) {
                    stie[j + 1] = stie[j]; j--;
                }
                stie[j + 1] = key;
            }
        }
        __syncthreads();
        if (need > 0) {
            for (int j = tid; j < S; j += K2_THREADS) {
                uint2 e = ss[j];
                if (e.x > Tk) {
                    int a = (int)(e.y & 0x1FFFFu);
                    if (cat) {
                        float x = cls[cls_index(n, a)];
                        b += softplusf(x); p += x;
                    } else {
                        int m = (int)(e.y >> 17);
                        pos_contrib(cls, deltas, gt, n, a, m, b, p, l);
                    }
                }
            }
            if (tid < r) {
                unsigned y = stie[tid];
                int a = (int)(y & 0x1FFFFu);
                if (cat) {
                    float x = cls[cls_index(n, a)];
                    b += softplusf(x); p += x;
                } else {
                    int m = (int)(y >> 17);
                    pos_contrib(cls, deltas, gt, n, a, m, b, p, l);
                }
            }
        }
    }

    // ---- block reduce + per-(image,cat) partials + global finalize ----
#pragma unroll
    for (int o = 16; o > 0; o >>= 1) {
        b += __shfl_down_sync(0xffffffffu, b, o);
        p += __shfl_down_sync(0xffffffffu, p, o);
        l += __shfl_down_sync(0xffffffffu, l, o);
    }
    if (lane == 0) { fwarp[wid][0] = b; fwarp[wid][1] = p; fwarp[wid][2] = l; }
    __syncthreads();

    if (tid == 0) {
        float sb = 0.f, sp = 0.f, sl_ = 0.f;
        for (int q = 0; q < K2_WARPS; q++) {
            sb += fwarp[q][0]; sp += fwarp[q][1]; sl_ += fwarp[q][2];
        }
        g_part[n][cat] = make_float4(sb, sp, sl_, (float)need);
        __threadfence();
        int ticket = atomicAdd(&g_ticket, 1);
        if (ticket == N_IMG * 2 - 1) {
            __threadfence();
            float cl = 0.f, bl = 0.f, fg = 0.f, bg = 0.f, pm = 0.f;
            for (int q = 0; q < N_IMG; q++) {
                volatile float* Pp = (volatile float*)&g_part[q][0];
                volatile float* Gg = (volatile float*)&g_part[q][1];
                float Pb = Pp[0], Pd = Pp[1], Pl = Pp[2], np = Pp[3];
                float Gb = Gg[0], Gd = Gg[1], nn = Gg[3];
                float denom = fmaxf(np + nn, 1.0f);
                cl += (Pb + Gb) / denom;
                bl += Pl / (fmaxf(np, 1.0f) * (float)N_IMG);
                fg += np; bg += nn;
                if (q == N_IMG - 1) pm = (Pd + Gd) / denom;
            }
            out[0] = cl; out[1] = bl; out[2] = bg; out[3] = fg; out[4] = pm;
            for (int i = 5; i < out_size; i++) out[i] = 0.0f;
            g_ticket = 0;
        }
    }
}

// ---------------- host launcher ----------------
extern "C" void kernel_launch(void* const* d_in, const int* in_sizes, int n_in,
                              void* d_out, int out_size) {
    (void)in_sizes; (void)n_in;
    const float* cls    = (const float*)d_in[0];
    const float* deltas = (const float*)d_in[1];
    const float* gt     = (const float*)d_in[2];
    float* out = (float*)d_out;

    Keys keys;
    for (int n = 0; n < N_IMG; n++) {
        unsigned K0, K1;
        tf2x32(0u, 42u, 0u, (unsigned)n, K0, K1);
        unsigned p0, p1, q0, q1;
        tf2x32(K0, K1, 0u, 0u, p0, p1);
        tf2x32(K0, K1, 0u, 1u, q0, q1);
        keys.kp0[n] = p0; keys.kp1[n] = p1;
        keys.kn0[n] = q0; keys.kn1[n] = q1;
    }

    dim3 g1(A_ANCH / K1_THREADS, N_IMG);                   // 405 x 8
    k_match<<<g1, K1_THREADS>>>(deltas, gt, keys);
    k_select<<<N_IMG * 2, K2_THREADS>>>(cls, deltas, gt, out, out_size);
}

// round 15
// speedup vs baseline: 1.2825x; 1.1096x over previous
#include <cuda_runtime.h>
#include <cstdint>
#include <cmath>

// ---------------- problem constants (fixed shapes) ----------------
#define N_IMG   8
#define K_ANC   9
#define HH      120
#define WW      120
#define M_GT    64
#define A_ANCH  (HH*WW*K_ANC)      /* 129600 */
#define HWSZ    (HH*WW)            /* 14400  */
#define IMG_SZ  1920.0f
#define KPOS    128
#define KNEG    60
#define CAP     4096                /* survivor capacity in shared */
#define TIE_CAP 128
#define RANK_MAX 1024               /* rank-select path limit */
#define MANT    8388608.0f          /* 2^23 */

// integer pre-filter thresholds on v = b>>9 (23-bit); v >= T -> high tier
#define TP_HI   6291456u            /* 0.75 * 2^23      : keep ~1/4   of positives */
#define TN_HI   8355840u            /* 0.99609375 * 2^23: keep ~1/256 of negatives */

// ---------------- static device scratch (no allocations) ----------------
__device__ uint2  g_pos[N_IMG * A_ANCH];   // low tier grows up, high tier grows down
__device__ uint2  g_neg[N_IMG * A_ANCH];
__device__ int    g_cnt[N_IMG * 4];        // [n][0]=pos_lo 1=pos_hi 2=neg_lo 3=neg_hi
__device__ float4 g_part[N_IMG][2];        // (bce, pred, l1, count)
__device__ int    g_ticket;                // zero-init; reset by last finalizer

struct Params {
    unsigned kp0[N_IMG], kp1[N_IMG], kn0[N_IMG], kn1[N_IMG];
    float hw2[K_ANC], hh2[K_ANC];          // per-k anchor half-sizes (host-computed)
};

// ---------------- threefry2x32 (JAX-exact) ----------------
__host__ __device__ __forceinline__ unsigned rotl32(unsigned x, int d) {
    return (x << d) | (x >> (32 - d));
}
__host__ __device__ __forceinline__ void tf2x32(unsigned k0, unsigned k1,
                                                unsigned x0, unsigned x1,
                                                unsigned& o0, unsigned& o1) {
    unsigned ks2 = k0 ^ k1 ^ 0x1BD11BDAu;
    x0 += k0; x1 += k1;
#define TFR(r) { x0 += x1; x1 = rotl32(x1, r); x1 ^= x0; }
    TFR(13) TFR(15) TFR(26) TFR(6)   x0 += k1;  x1 += ks2 + 1u;
    TFR(17) TFR(29) TFR(16) TFR(24)  x0 += ks2; x1 += k0  + 2u;
    TFR(13) TFR(15) TFR(26) TFR(6)   x0 += k0;  x1 += k1  + 3u;
    TFR(17) TFR(29) TFR(16) TFR(24)  x0 += k1;  x1 += ks2 + 4u;
    TFR(13) TFR(15) TFR(26) TFR(6)   x0 += ks2; x1 += k0  + 5u;
#undef TFR
    o0 = x0; o1 = x1;
}

// raw 23-bit uniform value: order/ties/zero-class identical to JAX's float u
__device__ __forceinline__ unsigned ubits_raw(unsigned k0, unsigned k1, int i) {
    unsigned o0, o1;
    tf2x32(k0, k1, 0u, (unsigned)i, o0, o1);
    return (o0 ^ o1) >> 9;
}

// ---------------- geometry helpers ----------------
__device__ __forceinline__ void anchor_box_k(float hw2, float hh2, int h, int w,
                                             float& ax1, float& ay1, float& ax2, float& ay2) {
    float cx = __fmul_rn((float)w + 0.5f, 16.0f);
    float cy = __fmul_rn((float)h + 0.5f, 16.0f);
    ax1 = __fsub_rn(cx, hw2); ay1 = __fsub_rn(cy, hh2);
    ax2 = __fadd_rn(cx, hw2); ay2 = __fadd_rn(cy, hh2);
}

// full recompute variant for pos_contrib (rare path; identical arithmetic)
__device__ __forceinline__ void anchor_box_full(int k, int h, int w,
                                                float& ax1, float& ay1, float& ax2, float& ay2) {
    int r = k / 3, s = k % 3;
    float scale = (s == 0) ? 8.0f : ((s == 1) ? 16.0f : 32.0f);
    float sq2 = sqrtf(2.0f), sqh = sqrtf(0.5f);
    float srw = (r == 0) ? sq2 : ((r == 1) ? 1.0f : sqh);
    float srh = (r == 0) ? sqh : ((r == 1) ? 1.0f : sq2);
    float wsz = __fmul_rn(16.0f * scale, srw);
    float hsz = __fmul_rn(16.0f * scale, srh);
    float hw2 = __fmul_rn(wsz, 0.5f), hh2 = __fmul_rn(hsz, 0.5f);
    anchor_box_k(hw2, hh2, h, w, ax1, ay1, ax2, ay2);
}

__device__ __forceinline__ void region_box(const float* __restrict__ deltas,
                                           int n, int k, int h, int w,
                                           float ax1, float ay1, float ax2, float ay2,
                                           float& rx1, float& ry1, float& rx2, float& ry2) {
    int db = ((n * 4 * K_ANC + k * 4) * HH + h) * WW + w;
    rx1 = fminf(fmaxf(__fadd_rn(ax1, deltas[db          ]), 0.0f), IMG_SZ);
    ry1 = fminf(fmaxf(__fadd_rn(ay1, deltas[db +   HWSZ ]), 0.0f), IMG_SZ);
    rx2 = fminf(fmaxf(__fadd_rn(ax2, deltas[db + 2*HWSZ ]), 0.0f), IMG_SZ);
    ry2 = fminf(fmaxf(__fadd_rn(ay2, deltas[db + 3*HWSZ ]), 0.0f), IMG_SZ);
}

__device__ __forceinline__ int cls_index(int n, int a) {
    int k = a % K_ANC; int hw = a / K_ANC; int w = hw % WW; int h = hw / WW;
    return ((n * K_ANC + k) * HH + h) * WW + w;
}

__device__ __forceinline__ float softplusf(float x) {
    return fmaxf(x, 0.0f) + log1pf(expf(-fabsf(x)));
}
__device__ __forceinline__ float sl1(float d) {
    float ad = fabsf(d);
    return (ad < 0.1f) ? (0.5f * d * d / 0.1f) : (ad - 0.05f);
}

__device__ void pos_contrib(const float* __restrict__ cls, const float* __restrict__ deltas,
                            const float* __restrict__ gt, int n, int a, int m,
                            float& bce, float& pred, float& l1) {
    int k = a % K_ANC; int hw = a / K_ANC; int w = hw % WW; int h = hw / WW;
    float ax1, ay1, ax2, ay2;
    anchor_box_full(k, h, w, ax1, ay1, ax2, ay2);
    float rx1, ry1, rx2, ry2;
    region_box(deltas, n, k, h, w, ax1, ay1, ax2, ay2, rx1, ry1, rx2, ry2);
    float aw = __fsub_rn(ax2, ax1), ah = __fsub_rn(ay2, ay1);
    float acx = ax1 + 0.5f * aw, acy = ay1 + 0.5f * ah;
    float bw = fmaxf(__fsub_rn(rx2, rx1), 1e-6f), bh = fmaxf(__fsub_rn(ry2, ry1), 1e-6f);
    float bcx = rx1 + 0.5f * bw, bcy = ry1 + 0.5f * bh;
    float tp0 = (bcx - acx) / aw, tp1 = (bcy - acy) / ah;
    float tp2 = logf(bw / aw),    tp3 = logf(bh / ah);
    const float* g = gt + (n * M_GT + m) * 4;
    float gw = fmaxf(__fsub_rn(g[2], g[0]), 1e-6f), gh = fmaxf(__fsub_rn(g[3], g[1]), 1e-6f);
    float gcx = g[0] + 0.5f * gw, gcy = g[1] + 0.5f * gh;
    float tg0 = (gcx - acx) / aw, tg1 = (gcy - acy) / ah;
    float tg2 = logf(gw / aw),    tg3 = logf(gh / ah);
    l1 += sl1(tp0 - tg0) + sl1(tp1 - tg1) + sl1(tp2 - tg2) + sl1(tp3 - tg3);
    float x = cls[((n * K_ANC + k) * HH + h) * WW + w];
    bce += softplusf(-x); pred += x;
}

// ---------------- kernel 1: region + IoU match + tiered compaction ----------------
// grid: (45, N_IMG*K_ANC); by -> (n, k); bx*320+tid -> hw. Warp grouping identical
// to the previous t-mapping (32 consecutive hw, block-uniform k).
#define K1_THREADS 320
__global__ __launch_bounds__(K1_THREADS, 6) void k_match(
        const float* __restrict__ deltas, const float* __restrict__ gt, Params prm) {
    int by = blockIdx.y;
    int n = by / K_ANC, k = by % K_ANC;            // block-uniform
    __shared__ float4 sg[M_GT];
    __shared__ float  sag[M_GT];
    __shared__ int    scnt[4];
    __shared__ int    sbase[4];
    __shared__ int    wboff[K1_THREADS / 32][4];
    int tid = threadIdx.x;
    if (tid < M_GT) {
        float4 b = reinterpret_cast<const float4*>(gt)[n * M_GT + tid];
        sg[tid] = b;
        sag[tid] = __fmul_rn(fmaxf(__fsub_rn(b.z, b.x), 0.0f),
                             fmaxf(__fsub_rn(b.w, b.y), 0.0f));
    }
    if (tid < 4) scnt[tid] = 0;
    __syncthreads();

    int hw = blockIdx.x * K1_THREADS + tid;        // < 14400
    int h = hw / WW; int w = hw % WW;
    int a = hw * K_ANC + k;

    float ax1, ay1, ax2, ay2;
    anchor_box_k(prm.hw2[k], prm.hh2[k], h, w, ax1, ay1, ax2, ay2);
    float rx1, ry1, rx2, ry2;
    region_box(deltas, n, k, h, w, ax1, ay1, ax2, ay2, rx1, ry1, rx2, ry2);
    float ab = __fmul_rn(fmaxf(__fsub_rn(rx2, rx1), 0.0f),
                         fmaxf(__fsub_rn(ry2, ry1), 0.0f));

    // warp-union bbox (skipped GTs provably have inter == 0 for every lane)
    float wx1 = rx1, wy1 = ry1, wx2 = rx2, wy2 = ry2;
#pragma unroll
    for (int o = 16; o > 0; o >>= 1) {
        wx1 = fminf(wx1, __shfl_xor_sync(0xffffffffu, wx1, o));
        wy1 = fminf(wy1, __shfl_xor_sync(0xffffffffu, wy1, o));
        wx2 = fmaxf(wx2, __shfl_xor_sync(0xffffffffu, wx2, o));
        wy2 = fmaxf(wy2, __shfl_xor_sync(0xffffffffu, wy2, o));
    }

    // ballot-compacted survivor masks: lane tests GT[lane] and GT[lane+32]
    int lane = tid & 31;
    float4 gA = sg[lane];
    float4 gB = sg[lane + 32];
    bool oA = (wx2 > gA.x) && (gA.z > wx1) && (wy2 > gA.y) && (gA.w > wy1);
    bool oB = (wx2 > gB.x) && (gB.z > wx1) && (wy2 > gB.y) && (gB.w > wy1);
    unsigned mA = __ballot_sync(0xffffffffu, oA);
    unsigned mB = __ballot_sync(0xffffffffu, oB);

    float best = 0.0f; int arg = 0;
    unsigned mm = mA; int mofs = 0;
#pragma unroll 1
    for (int half = 0; half < 2; half++) {
        while (mm) {
            int m = (__ffs(mm) - 1) + mofs;        // increasing m: first-tie preserved
            mm &= mm - 1;
            float4 g = sg[m];                      // uniform -> LDS broadcast
            float ix1 = fmaxf(rx1, g.x), iy1 = fmaxf(ry1, g.y);
            float ix2 = fminf(rx2, g.z), iy2 = fminf(ry2, g.w);
            float inter = __fmul_rn(fmaxf(__fsub_rn(ix2, ix1), 0.0f),
                                    fmaxf(__fsub_rn(iy2, iy1), 0.0f));
            float den = __fadd_rn(__fsub_rn(__fadd_rn(ab, sag[m]), inter), 1e-6f);
            if (inter > __fmul_rn(__fmul_rn(best, den), 0.9999995f) && inter > 0.0f) {
                float iou = __fdiv_rn(inter, den);
                if (iou > best) { best = iou; arg = m; }
            }
        }
        mm = mB; mofs = 32;
    }

    int match = (best >= 0.4f) ? arg : ((best < 0.1f) ? -1 : -2);
    unsigned ub = 0u;
    if (match >= 0)       ub = ubits_raw(prm.kp0[n], prm.kp1[n], a);
    else if (match == -1) ub = ubits_raw(prm.kn0[n], prm.kn1[n], a);
    bool isp = (match >= 0) && (ub != 0u);
    bool isn = (match == -1) && (ub != 0u);
    bool hip = isp && (ub >= TP_HI);
    bool hin = isn && (ub >= TN_HI);

    int wid = tid >> 5;
    unsigned m0 = __ballot_sync(0xffffffffu, isp && !hip);
    unsigned m1 = __ballot_sync(0xffffffffu, hip);
    unsigned m2 = __ballot_sync(0xffffffffu, isn && !hin);
    unsigned m3 = __ballot_sync(0xffffffffu, hin);
    if (lane == 0) {
        wboff[wid][0] = atomicAdd(&scnt[0], __popc(m0));
        wboff[wid][1] = atomicAdd(&scnt[1], __popc(m1));
        wboff[wid][2] = atomicAdd(&scnt[2], __popc(m2));
        wboff[wid][3] = atomicAdd(&scnt[3], __popc(m3));
    }
    __syncthreads();
    if (tid < 4) sbase[tid] = atomicAdd(&g_cnt[n * 4 + tid], scnt[tid]);
    __syncthreads();
    unsigned lm = (1u << lane) - 1u;
    if (isp) {
        uint2 e = make_uint2(ub, (unsigned)a | ((unsigned)arg << 17));
        if (hip) {
            int p = sbase[1] + wboff[wid][1] + __popc(m1 & lm);
            g_pos[n * A_ANCH + (A_ANCH - 1 - p)] = e;
        } else {
            int p = sbase[0] + wboff[wid][0] + __popc(m0 & lm);
            g_pos[n * A_ANCH + p] = e;
        }
    }
    if (isn) {
        uint2 e = make_uint2(ub, (unsigned)a);
        if (hin) {
            int p = sbase[3] + wboff[wid][3] + __popc(m3 & lm);
            g_neg[n * A_ANCH + (A_ANCH - 1 - p)] = e;
        } else {
            int p = sbase[2] + wboff[wid][2] + __popc(m2 & lm);
            g_neg[n * A_ANCH + p] = e;
        }
    }
}

// ---------------- kernel 2: exact top-K (rank-select fast path) + loss reduce ----------------
#define K2_THREADS 512
#define K2_WARPS   (K2_THREADS / 32)

__global__ __launch_bounds__(K2_THREADS) void k_select(
        const float* __restrict__ cls, const float* __restrict__ deltas,
        const float* __restrict__ gt, float* out, int out_size) {
    int bx = blockIdx.x;
    int n = bx >> 1, cat = bx & 1;                 // 0 = pos, 1 = neg
    int tid = threadIdx.x;
    int wid = tid >> 5, lane = tid & 31;
    const uint2* base = (cat ? g_neg : g_pos) + n * A_ANCH;

    __shared__ int sClo, sChi;
    if (tid == 0) {
        sClo = g_cnt[n * 4 + cat * 2 + 0];
        sChi = g_cnt[n * 4 + cat * 2 + 1];
        g_cnt[n * 4 + cat * 2 + 0] = 0;            // single-owner read+reset
        g_cnt[n * 4 + cat * 2 + 1] = 0;
    }
    __syncthreads();
    int Clo = sClo, Chi = sChi;
    int Ctot = Clo + Chi;
    int K = cat ? KNEG : KPOS;
    int need = min(K, Ctot);

    // segment view: high tier always; low tier only when high can't cover top-K
    const uint2* segA = base + (A_ANCH - Chi);
    int LA = Chi;
    int LB = (Chi >= need) ? 0 : Clo;
    int L = LA + LB;
    auto LD = [&](int i) -> uint2 { return (i < LA) ? segA[i] : base[i - LA]; };

    __shared__ uint2    ss[CAP];
    __shared__ unsigned stie[TIE_CAP];
    __shared__ int      swarp[K2_WARPS][3];
    __shared__ float    fwarp[K2_WARPS][3];
    __shared__ int      stot[3];
    __shared__ unsigned sT;
    __shared__ int      sS, sLo, sHi, sFlag;
    __shared__ int      hist[256];
    __shared__ unsigned s_sel;
    __shared__ int      s_needr, s_tiecnt, scap;

    unsigned T0 = 1u, T1 = 1u;
    {
        float invC = 1.0f / (float)max(Ctot, 1);
        float u0 = 1.0f - __fmul_rn(1.4f, (float)K) * invC;   // tight: E[S] ~ 1.4K
        float u1 = 1.0f - (float)(8 * K) * invC;
        T0 = (u0 <= 0.0f) ? 1u : max(1u, (unsigned)(u0 * MANT));
        T1 = (u1 <= 0.0f) ? 1u : max(1u, (unsigned)(u1 * MANT));
    }
    if (tid == 0) scap = 0;
    __syncthreads();

    // ---- single scan: 3 counts + opportunistic atomic capture at T0 ----
    int c0 = 0, c1 = 0, c2 = 0;
    for (int i = tid; i < L; i += K2_THREADS) {
        uint2 e = LD(i);
        unsigned v = e.x;
        c0 += (v >= T0); c1 += (v >= T1); c2++;
        if (v >= T0) {
            int p = atomicAdd(&scap, 1);
            if (p < CAP) ss[p] = e;                // order-free: rank/radix later
        }
    }
#pragma unroll
    for (int o = 16; o > 0; o >>= 1) {
        c0 += __shfl_down_sync(0xffffffffu, c0, o);
        c1 += __shfl_down_sync(0xffffffffu, c1, o);
        c2 += __shfl_down_sync(0xffffffffu, c2, o);
    }
    if (lane == 0) { swarp[wid][0] = c0; swarp[wid][1] = c1; swarp[wid][2] = c2; }
    __syncthreads();
    if (tid < 3) {
        int s = 0;
        for (int q = 0; q < K2_WARPS; q++) s += swarp[q][tid];
        stot[tid] = s;
    }
    __syncthreads();

    int S;
    if (stot[0] >= need && stot[0] <= CAP) {
        S = stot[0];                               // common path: capture already done
    } else {
        unsigned T;
        if (stot[1] >= need && stot[1] <= CAP)      { T = T1; S = stot[1]; }
        else if (stot[2] <= CAP)                    { T = 1u; S = stot[2]; }
        else {
            // exactness backstop: binary-search tightest threshold in [need, CAP]
            if (tid == 0) {
                if (stot[1] >= need) { sLo = (int)T1; sHi = (int)T0; sT = T1; sS = stot[1]; }
                else                 { sLo = (int)1u; sHi = (int)T1; sT = 1u; sS = stot[2]; }
                sFlag = 1;
            }
            __syncthreads();
            for (int iter = 0; iter < 34 && sFlag; iter++) {
                unsigned lo = (unsigned)sLo, hi = (unsigned)sHi;
                if (hi - lo <= 1u) break;
                unsigned mid = lo + ((hi - lo) >> 1);
                int c = 0;
                for (int i = tid; i < L; i += K2_THREADS) c += (LD(i).x >= mid);
#pragma unroll
                for (int o = 16; o > 0; o >>= 1) c += __shfl_down_sync(0xffffffffu, c, o);
                if (lane == 0) swarp[wid][0] = c;
                __syncthreads();
                if (tid == 0) {
                    int s = 0;
                    for (int q = 0; q < K2_WARPS; q++) s += swarp[q][0];
                    if (s >= need) { sLo = (int)mid; sT = mid; sS = s; }
                    else           { sHi = (int)mid; }
                    if (sS <= CAP) sFlag = 0;
                }
                __syncthreads();
            }
            __syncthreads();
            T = sT; S = min(sS, CAP);
        }
        // recapture at T (rare path)
        if (tid == 0) scap = 0;
        __syncthreads();
        for (int i = tid; i < L; i += K2_THREADS) {
            uint2 e = LD(i);
            if (e.x >= T) { int p = atomicAdd(&scap, 1); if (p < CAP) ss[p] = e; }
        }
        __syncthreads();
    }
    __syncthreads();                               // ss[] fully visible

    float b = 0.0f, p = 0.0f, l = 0.0f;

    if (S <= RANK_MAX) {
        // ---- exact rank-select (lax.top_k semantics, single phase, no syncs) ----
        for (int j = tid; j < S; j += K2_THREADS) {
            uint2 e = ss[j];
            unsigned v = e.x, aj = e.y & 0x1FFFFu;
            int rank = 0;
            for (int i = 0; i < S; i++) {          // lockstep -> LDS broadcast
                uint2 f = ss[i];
                unsigned ai = f.y & 0x1FFFFu;
                rank += (f.x > v) || (f.x == v && ai < aj);
            }
            if (rank < need) {
                int a = (int)aj;
                if (cat) {
                    float x = cls[cls_index(n, a)];
                    b += softplusf(x); p += x;
                } else {
                    int m = (int)(e.y >> 17);
                    pos_contrib(cls, deltas, gt, n, a, m, b, p, l);
                }
            }
        }
    } else {
        // ---- fallback: radix select + tie handling (rare: S > RANK_MAX) ----
        if (tid == 0) { s_sel = 0u; s_needr = need; s_tiecnt = 0; }
        __syncthreads();
#pragma unroll 1
        for (int ps = 0; ps < 4; ps++) {
            int shift = 24 - 8 * ps;
            if (tid < 256) hist[tid] = 0;
            __syncthreads();
            unsigned selhi = s_sel;
            int nr = s_needr;
            for (int j = tid; j < S; j += K2_THREADS) {
                unsigned v = ss[j].x;
                if (ps == 0 || (v >> (shift + 8)) == (selhi >> (shift + 8)))
                    atomicAdd(&hist[(v >> shift) & 0xFFu], 1);
            }
            __syncthreads();
            if (wid == 0 && nr > 0) {
                int bbase = 255 - 8 * lane;
                int ch = 0;
#pragma unroll
                for (int q = 0; q < 8; q++) ch += hist[bbase - q];
                int pre = ch;
#pragma unroll
                for (int o = 1; o < 32; o <<= 1) {
                    int v = __shfl_up_sync(0xffffffffu, pre, o);
                    if (lane >= o) pre += v;
                }
                int excl = pre - ch;
                if (excl < nr && nr <= pre) {
                    int tgt = nr - excl, cum = 0;
                    for (int q = 0; q < 8; q++) {
                        int c = hist[bbase - q];
                        if (cum + c >= tgt) {
                            s_sel = selhi | ((unsigned)(bbase - q) << shift);
                            s_needr = tgt - cum;
                            break;
                        }
                        cum += c;
                    }
                }
            }
            __syncthreads();
        }
        unsigned Tk = s_sel;
        int r = s_needr;
        for (int j = tid; j < S; j += K2_THREADS) {
            if (ss[j].x == Tk) {
                int q = atomicAdd(&s_tiecnt, 1);
                if (q < TIE_CAP) stie[q] = ss[j].y;
            }
        }
        __syncthreads();
        if (tid == 0 && need > 0) {
            int c = min(s_tiecnt, TIE_CAP);
            for (int i = 1; i < c; i++) {
                unsigned key = stie[i]; int j = i - 1;
                while (j >= 0 && (stie[j] & 0x1FFFFu) > (key & 0x1FFFFu)) {
                    stie[j + 1] = stie[j]; j--;
                }
                stie[j + 1] = key;
            }
        }
        __syncthreads();
        if (need > 0) {
            for (int j = tid; j < S; j += K2_THREADS) {
                uint2 e = ss[j];
                if (e.x > Tk) {
                    int a = (int)(e.y & 0x1FFFFu);
                    if (cat) {
                        float x = cls[cls_index(n, a)];
                        b += softplusf(x); p += x;
                    } else {
                        int m = (int)(e.y >> 17);
                        pos_contrib(cls, deltas, gt, n, a, m, b, p, l);
                    }
                }
            }
            if (tid < r) {
                unsigned y = stie[tid];
                int a = (int)(y & 0x1FFFFu);
                if (cat) {
                    float x = cls[cls_index(n, a)];
                    b += softplusf(x); p += x;
                } else {
                    int m = (int)(y >> 17);
                    pos_contrib(cls, deltas, gt, n, a, m, b, p, l);
                }
            }
        }
    }

    // ---- block reduce + per-(image,cat) partials + global finalize ----
#pragma unroll
    for (int o = 16; o > 0; o >>= 1) {
        b += __shfl_down_sync(0xffffffffu, b, o);
        p += __shfl_down_sync(0xffffffffu, p, o);
        l += __shfl_down_sync(0xffffffffu, l, o);
    }
    if (lane == 0) { fwarp[wid][0] = b; fwarp[wid][1] = p; fwarp[wid][2] = l; }
    __syncthreads();

    if (tid == 0) {
        float sb = 0.f, sp = 0.f, sl_ = 0.f;
        for (int q = 0; q < K2_WARPS; q++) {
            sb += fwarp[q][0]; sp += fwarp[q][1]; sl_ += fwarp[q][2];
        }
        g_part[n][cat] = make_float4(sb, sp, sl_, (float)need);
        __threadfence();
        int ticket = atomicAdd(&g_ticket, 1);
        if (ticket == N_IMG * 2 - 1) {
            __threadfence();
            float cl = 0.f, bl = 0.f, fg = 0.f, bg = 0.f, pm = 0.f;
            for (int q = 0; q < N_IMG; q++) {
                volatile float* Pp = (volatile float*)&g_part[q][0];
                volatile float* Gg = (volatile float*)&g_part[q][1];
                float Pb = Pp[0], Pd = Pp[1], Pl = Pp[2], np = Pp[3];
                float Gb = Gg[0], Gd = Gg[1], nn = Gg[3];
                float denom = fmaxf(np + nn, 1.0f);
                cl += (Pb + Gb) / denom;
                bl += Pl / (fmaxf(np, 1.0f) * (float)N_IMG);
                fg += np; bg += nn;
                if (q == N_IMG - 1) pm = (Pd + Gd) / denom;
            }
            out[0] = cl; out[1] = bl; out[2] = bg; out[3] = fg; out[4] = pm;
            for (int i = 5; i < out_size; i++) out[i] = 0.0f;
            g_ticket = 0;
        }
    }
}

// ---------------- host launcher ----------------
extern "C" void kernel_launch(void* const* d_in, const int* in_sizes, int n_in,
                              void* d_out, int out_size) {
    (void)in_sizes; (void)n_in;
    const float* cls    = (const float*)d_in[0];
    const float* deltas = (const float*)d_in[1];
    const float* gt     = (const float*)d_in[2];
    float* out = (float*)d_out;

    Params prm;
    for (int n = 0; n < N_IMG; n++) {
        unsigned K0, K1;
        tf2x32(0u, 42u, 0u, (unsigned)n, K0, K1);
        unsigned p0, p1, q0, q1;
        tf2x32(K0, K1, 0u, 0u, p0, p1);
        tf2x32(K0, K1, 0u, 1u, q0, q1);
        prm.kp0[n] = p0; prm.kp1[n] = p1;
        prm.kn0[n] = q0; prm.kn1[n] = q1;
    }
    // per-k anchor half-sizes, identical IEEE float ops to device version
    for (int k = 0; k < K_ANC; k++) {
        int r = k / 3, s = k % 3;
        float scale = (s == 0) ? 8.0f : ((s == 1) ? 16.0f : 32.0f);
        float sq2 = sqrtf(2.0f), sqh = sqrtf(0.5f);
        float srw = (r == 0) ? sq2 : ((r == 1) ? 1.0f : sqh);
        float srh = (r == 0) ? sqh : ((r == 1) ? 1.0f : sq2);
        float wsz = 16.0f * scale * srw;
        float hsz = 16.0f * scale * srh;
        prm.hw2[k] = wsz * 0.5f;
        prm.hh2[k] = hsz * 0.5f;
    }

    dim3 g1(HWSZ / K1_THREADS, N_IMG * K_ANC);             // 45 x 72
    k_match<<<g1, K1_THREADS>>>(deltas, gt, prm);
    k_select<<<N_IMG * 2, K2_THREADS>>>(cls, deltas, gt, out, out_size);
}